// round 10
// baseline (speedup 1.0000x reference)
#include <cuda_runtime.h>
#include <cuda_bf16.h>
#include <cstdint>

#define NN 4096
#define DM 1024
#define KW 10
#define NQKV 3072
#define MAXNNZ 256

typedef __nv_bfloat16 bf16;

// ---------------------------------------------------------------------------
// Scratch (device globals; allocation-free)
// ---------------------------------------------------------------------------
__device__ __align__(256) float g_dng   [(size_t)NN*NN];
__device__ __align__(256) float g_scores[(size_t)NN*NN];
__device__ __align__(256) float g_P     [(size_t)KW*NN*DM];
__device__ __align__(256) float g_Kf    [(size_t)NN*DM];
__device__ __align__(256) float g_bcat  [NQKV];
__device__ __align__(256) float g_row[NN];
__device__ __align__(256) float g_col[NN];
__device__ __align__(256) int   g_nnzidx[(size_t)NN*MAXNNZ];
__device__ __align__(256) int   g_nnzcnt[NN];

__device__ __align__(256) bf16 g_Shi [(size_t)NN*NN];
__device__ __align__(256) bf16 g_Slo [(size_t)NN*NN];
__device__ __align__(256) bf16 g_xhi [(size_t)NN*NN];
__device__ __align__(256) bf16 g_xlo [(size_t)NN*NN];
__device__ __align__(256) bf16 g_athi[(size_t)NN*NN];
__device__ __align__(256) bf16 g_atlo[(size_t)NN*NN];
__device__ __align__(256) bf16 g_Wshi[(size_t)KW*NN*DM];
__device__ __align__(256) bf16 g_Wslo[(size_t)KW*NN*DM];
__device__ __align__(256) bf16 g_hhi [(size_t)NN*DM];
__device__ __align__(256) bf16 g_hlo [(size_t)NN*DM];
__device__ __align__(256) bf16 g_QKVhi[(size_t)NN*NQKV];  // [Q|K|V] split (K block unused)
__device__ __align__(256) bf16 g_QKVlo[(size_t)NN*NQKV];
__device__ __align__(256) bf16 g_KThi[(size_t)DM*NN];     // K^T split
__device__ __align__(256) bf16 g_KTlo[(size_t)DM*NN];
__device__ __align__(256) bf16 g_aohi[(size_t)NN*DM];
__device__ __align__(256) bf16 g_aolo[(size_t)NN*DM];
__device__ __align__(256) bf16 g_Wcathi[(size_t)DM*NQKV]; // [Wq|Wk|Wv] split
__device__ __align__(256) bf16 g_Wcatlo[(size_t)DM*NQKV];
__device__ __align__(256) bf16 g_Wohi[(size_t)DM*NN];
__device__ __align__(256) bf16 g_Wolo[(size_t)DM*NN];

// ---------------------------------------------------------------------------
// Streams / events (static init; pre-checkpoint)
// ---------------------------------------------------------------------------
static cudaStream_t g_s2 = nullptr;
static cudaEvent_t  g_evF = nullptr, g_evJ = nullptr, g_evW = nullptr;
static struct _AsyncInit {
    _AsyncInit() {
        if (cudaStreamCreateWithFlags(&g_s2, cudaStreamNonBlocking) != cudaSuccess) g_s2 = nullptr;
        if (cudaEventCreateWithFlags(&g_evF, cudaEventDisableTiming) != cudaSuccess) g_evF = nullptr;
        if (cudaEventCreateWithFlags(&g_evJ, cudaEventDisableTiming) != cudaSuccess) g_evJ = nullptr;
        if (cudaEventCreateWithFlags(&g_evW, cudaEventDisableTiming) != cudaSuccess) g_evW = nullptr;
    }
} g_asyncInit;

// ---------------------------------------------------------------------------
// PTX helpers
// ---------------------------------------------------------------------------
__device__ __forceinline__ void cp16_s(uint32_t s, const void* g) {
    asm volatile("cp.async.cg.shared.global [%0], [%1], 16;\n" :: "r"(s), "l"(g));
}
__device__ __forceinline__ void cp_commit() { asm volatile("cp.async.commit_group;\n"); }
template<int W> __device__ __forceinline__ void cp_wait() {
    asm volatile("cp.async.wait_group %0;\n" :: "n"(W));
}
__device__ __forceinline__ void ldsm4(uint32_t& r0, uint32_t& r1, uint32_t& r2, uint32_t& r3,
                                      uint32_t addr) {
    asm volatile("ldmatrix.sync.aligned.m8n8.x4.shared.b16 {%0,%1,%2,%3}, [%4];\n"
                 : "=r"(r0), "=r"(r1), "=r"(r2), "=r"(r3) : "r"(addr));
}
__device__ __forceinline__ void ldsm4t(uint32_t& r0, uint32_t& r1, uint32_t& r2, uint32_t& r3,
                                       uint32_t addr) {
    asm volatile("ldmatrix.sync.aligned.m8n8.x4.trans.shared.b16 {%0,%1,%2,%3}, [%4];\n"
                 : "=r"(r0), "=r"(r1), "=r"(r2), "=r"(r3) : "r"(addr));
}
__device__ __forceinline__ void mma16816(float* c, const uint32_t* a, const uint32_t* b) {
    asm volatile("mma.sync.aligned.m16n8k16.row.col.f32.bf16.bf16.f32 "
                 "{%0,%1,%2,%3}, {%4,%5,%6,%7}, {%8,%9}, {%0,%1,%2,%3};\n"
                 : "+f"(c[0]), "+f"(c[1]), "+f"(c[2]), "+f"(c[3])
                 : "r"(a[0]), "r"(a[1]), "r"(a[2]), "r"(a[3]), "r"(b[0]), "r"(b[1]));
}

__device__ __forceinline__ void split2_store(bf16* hi, bf16* lo, size_t idx, float2 v) {
    bf16 hx = __float2bfloat16(v.x), hy = __float2bfloat16(v.y);
    bf16 lx = __float2bfloat16(v.x - __bfloat162float(hx));
    bf16 ly = __float2bfloat16(v.y - __bfloat162float(hy));
    *(__nv_bfloat162*)&hi[idx] = __halves2bfloat162(hx, hy);
    *(__nv_bfloat162*)&lo[idx] = __halves2bfloat162(lx, ly);
}

// ---------------------------------------------------------------------------
// bf16 split GEMM (tensor cores): 128x128 tile, K-chunk 64, 256 threads,
// 3-stage cp.async pipeline, swizzled A and B tiles (conflict-free ldmatrix).
// Compensated product: Ah@Bh + Ah@Bl + Al@Bh (SPLIT) else Ah@Bh.
// EPI 0: C=acc ; 2: C=alpha*acc+D ; 3: C=relu(acc+bias+D)
// EPI 4: t=acc+bias; cols[1024,2048) fp32->C only (ld DM); others split->OHi/OLo (ldo)
// EPI 5: split-store acc -> OHi/OLo (ldo)
// ---------------------------------------------------------------------------
#define A_TILE_B 16384          // 128 rows * 128B (64 bf16 cols), swizzled
#define B_TILE_B 16384          // 64 rows * 256B (128 bf16 cols), swizzled
#define STAGE_B  (2*A_TILE_B + 2*B_TILE_B)   // 65536
#define STAGES   3
#define GEMM_SMEM (STAGES * STAGE_B)         // 196608

template<int EPI, bool SPLIT>
__global__ void __launch_bounds__(256, 1)
bgemm(const bf16* __restrict__ Ah, const bf16* __restrict__ Al,
      const bf16* __restrict__ Bh, const bf16* __restrict__ Bl,
      float* __restrict__ C, const float* __restrict__ D,
      const float* __restrict__ bias,
      bf16* __restrict__ OHi, bf16* __restrict__ OLo,
      int M, int N, int K, int lda, int ldb, int ldo,
      size_t aSz, size_t bSz, size_t cSz, float alpha)
{
    extern __shared__ char smem[];
    constexpr int NSPL = SPLIT ? 2 : 1;

    const int t    = threadIdx.x;
    const int lane = t & 31;
    const int wid  = t >> 5;
    const int m0   = blockIdx.y * 128;
    const int n0   = blockIdx.x * 128;
    const int z    = blockIdx.z;

    const bf16* Ahp = Ah + (size_t)z * aSz;
    const bf16* Alp = SPLIT ? (Al + (size_t)z * aSz) : nullptr;
    const bf16* Bhp = Bh + (size_t)z * bSz;
    const bf16* Blp = SPLIT ? (Bl + (size_t)z * bSz) : nullptr;
    float*      Cp  = C ? (C + (size_t)z * cSz) : nullptr;

    const int m0w = (wid & 1) * 64;
    const int n0w = (wid >> 1) * 32;

    const uint32_t smemU = (uint32_t)__cvta_generic_to_shared(smem);

    float acc[4][4][4] = {};
    const int nch = K >> 6;   // K / 64

    const int ar = t >> 3, ac = t & 7;      // A: 4 iters of (row += 32)
    const int br = t >> 4, bc = t & 15;     // B: 4 iters of (row += 16)

    auto load_stage = [&](int buf, int kc) {
        const int kg = kc << 6;
        const uint32_t sb = smemU + buf * STAGE_B;
#pragma unroll
        for (int it = 0; it < 4; it++) {
            int r = ar + it * 32, c = ac;
            uint32_t dst = sb + r * 128 + (((c ^ (r & 7)) & 7) << 4);
            cp16_s(dst, Ahp + (size_t)(m0 + r) * lda + kg + c * 8);
            if (SPLIT)
                cp16_s(dst + A_TILE_B, Alp + (size_t)(m0 + r) * lda + kg + c * 8);
        }
#pragma unroll
        for (int it = 0; it < 4; it++) {
            int r = br + it * 16, c = bc;
            uint32_t dst = sb + 2 * A_TILE_B + r * 256 + ((c ^ (r & 7)) << 4);
            cp16_s(dst, Bhp + (size_t)(kg + r) * ldb + n0 + c * 8);
            if (SPLIT)
                cp16_s(dst + B_TILE_B, Blp + (size_t)(kg + r) * ldb + n0 + c * 8);
        }
    };

    auto compute_stage = [&](int buf) {
        const uint32_t sb = smemU + buf * STAGE_B;
        const int arow  = m0w + (lane & 15);
        const int krow0 = lane & 15;
        const int chAdd = (n0w >> 3) + (lane >> 4);
#pragma unroll
        for (int ks = 0; ks < 4; ks++) {
            uint32_t a[NSPL][4][4];
            uint32_t b[NSPL][4][2];
#pragma unroll
            for (int s = 0; s < NSPL; s++) {
#pragma unroll
                for (int mt = 0; mt < 4; mt++) {
                    int row = arow + mt * 16;
                    int ka  = (ks * 2 + (lane >> 4)) ^ (row & 7);
                    uint32_t addr = sb + s * A_TILE_B + row * 128 + (ka << 4);
                    ldsm4(a[s][mt][0], a[s][mt][1], a[s][mt][2], a[s][mt][3], addr);
                }
            }
            const int krow = ks * 16 + krow0;
#pragma unroll
            for (int s = 0; s < NSPL; s++) {
#pragma unroll
                for (int nt = 0; nt < 2; nt++) {
                    int ch = (chAdd + nt * 2) ^ (krow & 7);
                    uint32_t addr = sb + 2 * A_TILE_B + s * B_TILE_B + krow * 256 + ch * 16;
                    uint32_t r0, r1, r2, r3;
                    ldsm4t(r0, r1, r2, r3, addr);
                    b[s][nt * 2][0] = r0;  b[s][nt * 2][1] = r1;
                    b[s][nt * 2 + 1][0] = r2;  b[s][nt * 2 + 1][1] = r3;
                }
            }
#pragma unroll
            for (int mt = 0; mt < 4; mt++) {
#pragma unroll
                for (int nj = 0; nj < 4; nj++) {
                    mma16816(acc[mt][nj], a[0][mt], b[0][nj]);
                    if (SPLIT) {
                        mma16816(acc[mt][nj], a[0][mt], b[1][nj]);
                        mma16816(acc[mt][nj], a[1][mt], b[0][nj]);
                    }
                }
            }
        }
    };

    load_stage(0, 0); cp_commit();
    load_stage(1, 1); cp_commit();
    cp_wait<1>();
    __syncthreads();

    for (int i = 0; i < nch; i++) {
        if (i + 2 < nch) load_stage((i + 2) % STAGES, i + 2);
        cp_commit();
        compute_stage(i % STAGES);
        cp_wait<1>();
        __syncthreads();
    }

    // epilogue
#pragma unroll
    for (int mt = 0; mt < 4; mt++) {
        int r0 = m0 + m0w + mt * 16 + (lane >> 2);
        int r1 = r0 + 8;
#pragma unroll
        for (int nj = 0; nj < 4; nj++) {
            int c = n0 + n0w + nj * 8 + (lane & 3) * 2;
            float2 v0 = make_float2(acc[mt][nj][0], acc[mt][nj][1]);
            float2 v1 = make_float2(acc[mt][nj][2], acc[mt][nj][3]);
            if (EPI == 3 || EPI == 4) {
                float2 bz = *(const float2*)&bias[c];
                v0.x += bz.x; v0.y += bz.y;
                v1.x += bz.x; v1.y += bz.y;
            }
            if (EPI == 2) {
                float2 d0 = *(const float2*)&D[(size_t)r0 * N + c];
                float2 d1 = *(const float2*)&D[(size_t)r1 * N + c];
                v0.x = fmaf(v0.x, alpha, d0.x); v0.y = fmaf(v0.y, alpha, d0.y);
                v1.x = fmaf(v1.x, alpha, d1.x); v1.y = fmaf(v1.y, alpha, d1.y);
            }
            if (EPI == 3) {
                float2 d0 = *(const float2*)&D[(size_t)r0 * N + c];
                float2 d1 = *(const float2*)&D[(size_t)r1 * N + c];
                v0.x = fmaxf(v0.x + d0.x, 0.f); v0.y = fmaxf(v0.y + d0.y, 0.f);
                v1.x = fmaxf(v1.x + d1.x, 0.f); v1.y = fmaxf(v1.y + d1.y, 0.f);
            }
            if (EPI == 4) {
                if (c >= DM && c < 2 * DM) {      // K block -> fp32 side store only
                    *(float2*)&C[(size_t)r0 * DM + (c - DM)] = v0;
                    *(float2*)&C[(size_t)r1 * DM + (c - DM)] = v1;
                } else {                          // Q and V blocks -> split store
                    split2_store(OHi, OLo, (size_t)r0 * ldo + c, v0);
                    split2_store(OHi, OLo, (size_t)r1 * ldo + c, v1);
                }
            } else if (EPI == 5) {
                split2_store(OHi, OLo, (size_t)r0 * ldo + c, v0);
                split2_store(OHi, OLo, (size_t)r1 * ldo + c, v1);
            } else {
                *(float2*)&Cp[(size_t)r0 * N + c] = v0;
                *(float2*)&Cp[(size_t)r1 * N + c] = v1;
            }
        }
    }
}

// ---------------------------------------------------------------------------
// Elementwise / conversion kernels
// ---------------------------------------------------------------------------
__device__ __forceinline__ void split4_store(bf16* hi, bf16* lo, size_t i4, float4 v) {
    bf16 hx = __float2bfloat16(v.x), hy = __float2bfloat16(v.y);
    bf16 hz = __float2bfloat16(v.z), hw = __float2bfloat16(v.w);
    bf16 lx = __float2bfloat16(v.x - __bfloat162float(hx));
    bf16 ly = __float2bfloat16(v.y - __bfloat162float(hy));
    bf16 lz = __float2bfloat16(v.z - __bfloat162float(hz));
    bf16 lw = __float2bfloat16(v.w - __bfloat162float(hw));
    ((__nv_bfloat162*)hi)[2 * i4]     = __halves2bfloat162(hx, hy);
    ((__nv_bfloat162*)hi)[2 * i4 + 1] = __halves2bfloat162(hz, hw);
    ((__nv_bfloat162*)lo)[2 * i4]     = __halves2bfloat162(lx, ly);
    ((__nv_bfloat162*)lo)[2 * i4 + 1] = __halves2bfloat162(lz, lw);
}

// 64B per thread (4 independent float4 loads first -> MLP=4)
__global__ void split_kernel(const float* __restrict__ src, bf16* __restrict__ hi,
                             bf16* __restrict__ lo)
{
    size_t g = ((size_t)blockIdx.x * blockDim.x + threadIdx.x) * 4;
    float4 v0 = ((const float4*)src)[g];
    float4 v1 = ((const float4*)src)[g + 1];
    float4 v2 = ((const float4*)src)[g + 2];
    float4 v3 = ((const float4*)src)[g + 3];
    split4_store(hi, lo, g, v0);
    split4_store(hi, lo, g + 1, v1);
    split4_store(hi, lo, g + 2, v2);
    split4_store(hi, lo, g + 3, v3);
}

// column-concat [Wq|Wk|Wv] ([DM,DM] each) -> split [DM, 3072]; 2 i4 per thread
__global__ void catsplit3_kernel(const float* __restrict__ Wq, const float* __restrict__ Wk,
                                 const float* __restrict__ Wv,
                                 bf16* __restrict__ hi, bf16* __restrict__ lo)
{
    size_t g = (size_t)blockIdx.x * blockDim.x + threadIdx.x;
#pragma unroll
    for (int u = 0; u < 2; u++) {
        size_t i4 = 2 * g + u;
        int k  = (int)(i4 / (NQKV / 4));
        int nq = (int)(i4 % (NQKV / 4));
        const float* src = (nq < 256) ? &Wq[(size_t)k * DM + nq * 4]
                         : (nq < 512) ? &Wk[(size_t)k * DM + (nq - 256) * 4]
                                      : &Wv[(size_t)k * DM + (nq - 512) * 4];
        float4 v = *(const float4*)src;
        split4_store(hi, lo, i4, v);
    }
}

__global__ void bcat_kernel(const float* __restrict__ bq, const float* __restrict__ bk,
                            const float* __restrict__ bv, float* __restrict__ o)
{
    int i = blockIdx.x * 256 + threadIdx.x;
    if (i < NQKV)
        o[i] = (i < DM) ? bq[i] : (i < 2 * DM) ? bk[i - DM] : bv[i - 2 * DM];
}

// split + transpose: src [R,C] fp32 -> hiT/loT [C,R] bf16
__global__ void splitT_kernel(const float* __restrict__ src, bf16* __restrict__ hiT,
                              bf16* __restrict__ loT, int R, int Cc)
{
    __shared__ float tile[32][33];
    int c0 = blockIdx.x * 32, r0 = blockIdx.y * 32;
    int tx = threadIdx.x, ty = threadIdx.y;
    for (int i = ty; i < 32; i += 8)
        tile[i][tx] = src[(size_t)(r0 + i) * Cc + c0 + tx];
    __syncthreads();
    for (int i = ty; i < 32; i += 8) {
        float v = tile[tx][i];
        bf16 h = __float2bfloat16(v);
        bf16 l = __float2bfloat16(v - __bfloat162float(h));
        size_t o = (size_t)(c0 + i) * R + r0 + tx;
        hiT[o] = h; loT[o] = l;
    }
}

__global__ void zero_kernel(float* __restrict__ p, int n)
{
    int i = blockIdx.x * blockDim.x + threadIdx.x;
    if (i < n) p[i] = 0.f;
}

__global__ void rowsum_kernel(const float* __restrict__ A, float* __restrict__ rowv)
{
    int warp = threadIdx.x >> 5, lane = threadIdx.x & 31;
    int row = blockIdx.x * 8 + warp;
    const float4* p = (const float4*)(A + (size_t)row * NN);
    float s = 0.f;
#pragma unroll
    for (int i = 0; i < 32; i++) {
        float4 v = p[lane + i * 32];
        s += v.x + v.y + v.z + v.w;
    }
#pragma unroll
    for (int o = 16; o; o >>= 1) s += __shfl_down_sync(0xffffffffu, s, o);
    if (!lane) rowv[row] = s;
}

__global__ void colsum_kernel(const float* __restrict__ A, float* __restrict__ colv)
{
    int j = blockIdx.x * 256 + threadIdx.x;
    int i0 = blockIdx.y * 256;
    float s = 0.f;
    for (int i = 0; i < 256; i++) s += A[(size_t)(i0 + i) * NN + j];
    atomicAdd(&colv[j], s);
}

__global__ void build_nnz_kernel(const float* __restrict__ A, int* __restrict__ idx,
                                 int* __restrict__ cnt)
{
    int row = blockIdx.x;
    __shared__ int c;
    if (threadIdx.x == 0) c = 0;
    __syncthreads();
    for (int col = threadIdx.x; col < NN; col += 256) {
        if (A[(size_t)row * NN + col] != 0.f) {
            int p = atomicAdd(&c, 1);
            if (p < MAXNNZ) idx[(size_t)row * MAXNNZ + p] = col;
        }
    }
    __syncthreads();
    if (threadIdx.x == 0) cnt[row] = (c < MAXNNZ) ? c : MAXNNZ;
}

// sparse inter + simfuse fused
__global__ void __launch_bounds__(256)
simfuse_sparse_kernel(const float* __restrict__ A, const float* __restrict__ G,
                      const int* __restrict__ idx, const int* __restrict__ cnt,
                      const float* __restrict__ rowv, const float* __restrict__ colv,
                      bf16* __restrict__ Shi, bf16* __restrict__ Slo)
{
    const int row = blockIdx.x;
    const int t = threadIdx.x;

    __shared__ int sidx[MAXNNZ];
    const int n = cnt[row];
    for (int e = t; e < n; e += 256) sidx[e] = idx[(size_t)row * MAXNNZ + e];
    __syncthreads();

    float4 acc[4] = {};
    for (int e = 0; e < n; e++) {
        const float4* Aj = (const float4*)(A + (size_t)sidx[e] * NN);
#pragma unroll
        for (int m = 0; m < 4; m++) {
            float4 v = Aj[t + m * 256];
            acc[m].x += v.x; acc[m].y += v.y; acc[m].z += v.z; acc[m].w += v.w;
        }
    }

    const float r = rowv[row];
    const float4* Ai = (const float4*)(A + (size_t)row * NN);
    const float4* Gi = (const float4*)(G + (size_t)row * NN);
    bf16* hi = Shi + (size_t)row * NN;
    bf16* lo = Slo + (size_t)row * NN;
#pragma unroll
    for (int m = 0; m < 4; m++) {
        int f4 = t + m * 256;
        float4 v = acc[m];
        float4 a = Ai[f4];
        float4 g = Gi[f4];
        float4 c = *(const float4*)&colv[f4 * 4];
        float4 o;
        o.x = v.x / (r + c.x - v.x + 1e-6f) + a.x + g.x;
        o.y = v.y / (r + c.y - v.y + 1e-6f) + a.y + g.y;
        o.z = v.z / (r + c.z - v.z + 1e-6f) + a.z + g.z;
        o.w = v.w / (r + c.w - v.w + 1e-6f) + a.w + g.w;
        split4_store(hi, lo, (size_t)f4, o);
    }
}

__global__ void combine_ln_kernel(const float* __restrict__ P, const float* __restrict__ w,
                                  const float* __restrict__ bstk,
                                  const float* __restrict__ gamma, const float* __restrict__ beta,
                                  bf16* __restrict__ hhi, bf16* __restrict__ hlo)
{
    int n = blockIdx.x, t = threadIdx.x;
    float wn[KW];
#pragma unroll
    for (int k = 0; k < KW; k++) wn[k] = w[n * KW + k];
    float4 v = make_float4(0.f, 0.f, 0.f, 0.f);
#pragma unroll
    for (int k = 0; k < KW; k++) {
        float4 p = ((const float4*)(P + ((size_t)k * NN + n) * DM))[t];
        float4 b = ((const float4*)(bstk + (size_t)k * DM))[t];
        v.x = fmaf(wn[k], p.x + b.x, v.x);
        v.y = fmaf(wn[k], p.y + b.y, v.y);
        v.z = fmaf(wn[k], p.z + b.z, v.z);
        v.w = fmaf(wn[k], p.w + b.w, v.w);
    }
    float s  = v.x + v.y + v.z + v.w;
    float s2 = v.x * v.x + v.y * v.y + v.z * v.z + v.w * v.w;
    __shared__ float sS[8], sS2[8], sMean, sInv;
    int warp = t >> 5, lane = t & 31;
#pragma unroll
    for (int o = 16; o; o >>= 1) {
        s  += __shfl_down_sync(0xffffffffu, s, o);
        s2 += __shfl_down_sync(0xffffffffu, s2, o);
    }
    if (!lane) { sS[warp] = s; sS2[warp] = s2; }
    __syncthreads();
    if (t == 0) {
        float S = 0.f, S2 = 0.f;
        for (int i = 0; i < 8; i++) { S += sS[i]; S2 += sS2[i]; }
        float mean = S * (1.f / DM);
        float var  = S2 * (1.f / DM) - mean * mean;
        sMean = mean;
        sInv  = rsqrtf(var + 1e-5f);
    }
    __syncthreads();
    float mean = sMean, inv = sInv;
    float4 gg = ((const float4*)gamma)[t];
    float4 bb = ((const float4*)beta)[t];
    float4 o;
    o.x = (v.x - mean) * inv * gg.x + bb.x;
    o.y = (v.y - mean) * inv * gg.y + bb.y;
    o.z = (v.z - mean) * inv * gg.z + bb.z;
    o.w = (v.w - mean) * inv * gg.w + bb.w;
    split4_store(hhi + (size_t)n * DM, hlo + (size_t)n * DM, t, o);
}

__global__ void softmax_kernel(const float* __restrict__ S, bf16* __restrict__ Ohi,
                               bf16* __restrict__ Olo)
{
    int r = blockIdx.x, t = threadIdx.x;
    const float4* row = (const float4*)(S + (size_t)r * NN);
    float4 v[4];
    float mx = -1e30f;
#pragma unroll
    for (int i = 0; i < 4; i++) {
        v[i] = row[t + i * 256];
        mx = fmaxf(mx, fmaxf(fmaxf(v[i].x, v[i].y), fmaxf(v[i].z, v[i].w)));
    }
    __shared__ float sh[8];
    __shared__ float sbc;
    int warp = t >> 5, lane = t & 31;
#pragma unroll
    for (int o = 16; o; o >>= 1) mx = fmaxf(mx, __shfl_xor_sync(0xffffffffu, mx, o));
    if (!lane) sh[warp] = mx;
    __syncthreads();
    if (t == 0) {
        float m = sh[0];
        for (int i = 1; i < 8; i++) m = fmaxf(m, sh[i]);
        sbc = m;
    }
    __syncthreads();
    mx = sbc;
    float s = 0.f;
#pragma unroll
    for (int i = 0; i < 4; i++) {
        v[i].x = __expf(v[i].x - mx);
        v[i].y = __expf(v[i].y - mx);
        v[i].z = __expf(v[i].z - mx);
        v[i].w = __expf(v[i].w - mx);
        s += v[i].x + v[i].y + v[i].z + v[i].w;
    }
#pragma unroll
    for (int o = 16; o; o >>= 1) s += __shfl_xor_sync(0xffffffffu, s, o);
    __syncthreads();
    if (!lane) sh[warp] = s;
    __syncthreads();
    if (t == 0) {
        float z = 0.f;
        for (int i = 0; i < 8; i++) z += sh[i];
        sbc = 1.f / z;
    }
    __syncthreads();
    float inv = sbc;
    bf16* hi = Ohi + (size_t)r * NN;
    bf16* lo = Olo + (size_t)r * NN;
#pragma unroll
    for (int i = 0; i < 4; i++) {
        float4 o;
        o.x = v[i].x * inv; o.y = v[i].y * inv; o.z = v[i].z * inv; o.w = v[i].w * inv;
        split4_store(hi, lo, (size_t)(t + i * 256), o);
    }
}

// ---------------------------------------------------------------------------
// Host launcher
// ---------------------------------------------------------------------------
extern "C" void kernel_launch(void* const* d_in, const int* in_sizes, int n_in,
                              void* d_out, int out_size)
{
    const float* x     = (const float*)d_in[0];
    const float* A     = (const float*)d_in[1];
    const float* G     = (const float*)d_in[2];
    const float* w     = (const float*)d_in[3];
    const float* Wstk  = (const float*)d_in[4];
    const float* bstk  = (const float*)d_in[5];
    const float* Wq    = (const float*)d_in[6];
    const float* bq    = (const float*)d_in[7];
    const float* Wk    = (const float*)d_in[8];
    const float* bk    = (const float*)d_in[9];
    const float* Wv    = (const float*)d_in[10];
    const float* bv    = (const float*)d_in[11];
    const float* Wo    = (const float*)d_in[12];
    const float* bo    = (const float*)d_in[13];
    const float* gamma = (const float*)d_in[14];
    const float* beta  = (const float*)d_in[15];
    float* out = (float*)d_out;

    float *dng, *scores, *P, *Kf, *bcat, *rowv, *colv;
    int *nnzidx, *nnzcnt;
    bf16 *Shi, *Slo, *xhi, *xlo, *athi, *atlo, *Wshi, *Wslo, *hhi, *hlo;
    bf16 *QKVhi, *QKVlo, *KThi, *KTlo, *aohi, *aolo, *Wcathi, *Wcatlo, *Wohi, *Wolo;
    cudaGetSymbolAddress((void**)&dng, g_dng);
    cudaGetSymbolAddress((void**)&scores, g_scores);
    cudaGetSymbolAddress((void**)&P, g_P);
    cudaGetSymbolAddress((void**)&Kf, g_Kf);
    cudaGetSymbolAddress((void**)&bcat, g_bcat);
    cudaGetSymbolAddress((void**)&rowv, g_row);
    cudaGetSymbolAddress((void**)&colv, g_col);
    cudaGetSymbolAddress((void**)&nnzidx, g_nnzidx);
    cudaGetSymbolAddress((void**)&nnzcnt, g_nnzcnt);
    cudaGetSymbolAddress((void**)&Shi, g_Shi);
    cudaGetSymbolAddress((void**)&Slo, g_Slo);
    cudaGetSymbolAddress((void**)&xhi, g_xhi);
    cudaGetSymbolAddress((void**)&xlo, g_xlo);
    cudaGetSymbolAddress((void**)&athi, g_athi);
    cudaGetSymbolAddress((void**)&atlo, g_atlo);
    cudaGetSymbolAddress((void**)&Wshi, g_Wshi);
    cudaGetSymbolAddress((void**)&Wslo, g_Wslo);
    cudaGetSymbolAddress((void**)&hhi, g_hhi);
    cudaGetSymbolAddress((void**)&hlo, g_hlo);
    cudaGetSymbolAddress((void**)&QKVhi, g_QKVhi);
    cudaGetSymbolAddress((void**)&QKVlo, g_QKVlo);
    cudaGetSymbolAddress((void**)&KThi, g_KThi);
    cudaGetSymbolAddress((void**)&KTlo, g_KTlo);
    cudaGetSymbolAddress((void**)&aohi, g_aohi);
    cudaGetSymbolAddress((void**)&aolo, g_aolo);
    cudaGetSymbolAddress((void**)&Wcathi, g_Wcathi);
    cudaGetSymbolAddress((void**)&Wcatlo, g_Wcatlo);
    cudaGetSymbolAddress((void**)&Wohi, g_Wohi);
    cudaGetSymbolAddress((void**)&Wolo, g_Wolo);

    cudaFuncSetAttribute(bgemm<0, true>,  cudaFuncAttributeMaxDynamicSharedMemorySize, GEMM_SMEM);
    cudaFuncSetAttribute(bgemm<2, true>,  cudaFuncAttributeMaxDynamicSharedMemorySize, GEMM_SMEM);
    cudaFuncSetAttribute(bgemm<3, true>,  cudaFuncAttributeMaxDynamicSharedMemorySize, GEMM_SMEM);
    cudaFuncSetAttribute(bgemm<4, true>,  cudaFuncAttributeMaxDynamicSharedMemorySize, GEMM_SMEM);
    cudaFuncSetAttribute(bgemm<5, true>,  cudaFuncAttributeMaxDynamicSharedMemorySize, GEMM_SMEM);

    const size_t NDM = (size_t)NN * DM;
    const bool fork = (g_s2 != nullptr) && (g_evF != nullptr) && (g_evJ != nullptr) &&
                      (g_evW != nullptr);
    cudaStream_t sB = fork ? g_s2 : (cudaStream_t)0;
    dim3 tb(32, 8);

    // ======================= spine head (stream sB) =======================
    // W_stack split has NO dependency on x -> start immediately.
    split_kernel<<<(int)(KW * NDM / 4 / 1024), 256, 0, sB>>>(Wstk, Wshi, Wslo);

    // ---- stream 0 (concurrent): x split + weight conversions for QKV/out ----
    split_kernel<<<NN * (NN / 4) / 1024, 256>>>(x, xhi, xlo);
    if (fork) cudaEventRecord(g_evF, 0);          // gates P (needs xhi/xlo)

    catsplit3_kernel<<<DM * (NQKV / 4) / 512, 256>>>(Wq, Wk, Wv, Wcathi, Wcatlo);
    bcat_kernel<<<12, 256>>>(bq, bk, bv, bcat);
    split_kernel<<<DM * (NN / 4) / 1024, 256>>>(Wo, Wohi, Wolo);
    if (fork) cudaEventRecord(g_evW, 0);          // gates QKV (needs Wcat/bcat)

    // ======================= chain B spine (stream sB) =======================
    if (fork) cudaStreamWaitEvent(sB, g_evF, 0);

    // P_k = x @ W_k (batched)
    bgemm<0, true><<<dim3(8, 32, KW), 256, GEMM_SMEM, sB>>>(
        xhi, xlo, Wshi, Wslo, P, nullptr, nullptr, nullptr, nullptr,
        NN, DM, NN, NN, DM, 0, 0, NDM, NDM, 1.f);

    combine_ln_kernel<<<NN, 256, 0, sB>>>(P, w, bstk, gamma, beta, hhi, hlo);

    if (fork) cudaStreamWaitEvent(sB, g_evW, 0);

    // fused [Q|K|V] = h @ [Wq|Wk|Wv] + bcat; Q/V split stores + K fp32 side store
    bgemm<4, true><<<dim3(NQKV / 128, 32), 256, GEMM_SMEM, sB>>>(
        hhi, hlo, Wcathi, Wcatlo, Kf, nullptr, bcat, QKVhi, QKVlo,
        NN, NQKV, DM, DM, NQKV, NQKV, 0, 0, 0, 1.f);

    splitT_kernel<<<dim3(DM / 32, NN / 32), tb, 0, sB>>>(Kf, KThi, KTlo, NN, DM);

    if (fork) cudaEventRecord(g_evJ, sB);

    // ======================= chain A (stream 0) =======================
    zero_kernel<<<16, 256>>>(colv, NN);
    build_nnz_kernel<<<NN, 256>>>(A, nnzidx, nnzcnt);
    rowsum_kernel<<<NN / 8, 256>>>(A, rowv);
    colsum_kernel<<<dim3(16, 16), 256>>>(A, colv);

    // sparse inter=A@A + simfuse -> S split
    simfuse_sparse_kernel<<<NN, 256>>>(A, G, nnzidx, nnzcnt, rowv, colv, Shi, Slo);

    // dng = S @ x
    bgemm<0, true><<<dim3(32, 32), 256, GEMM_SMEM>>>(
        Shi, Slo, xhi, xlo, dng, nullptr, nullptr, nullptr, nullptr,
        NN, NN, NN, NN, NN, 0, 0, 0, 0, 1.f);

    // ======================= join =======================
    if (fork) cudaStreamWaitEvent(0, g_evJ, 0);

    // scores = Q @ K^T / 32 + dng
    bgemm<2, true><<<dim3(32, 32), 256, GEMM_SMEM>>>(
        QKVhi, QKVlo, KThi, KTlo, scores, dng, nullptr, nullptr, nullptr,
        NN, NN, DM, NQKV, NN, 0, 0, 0, 0, 0.03125f);

    softmax_kernel<<<NN, 256>>>(scores, athi, atlo);

    // ao = attn @ V  (V = QKV cols [2048,3072)); split-store ao
    bgemm<5, true><<<dim3(8, 32), 256, GEMM_SMEM>>>(
        athi, atlo, QKVhi + 2 * DM, QKVlo + 2 * DM, nullptr, nullptr, nullptr, aohi, aolo,
        NN, DM, NN, NN, NQKV, DM, 0, 0, 0, 1.f);

    // out = relu(ao @ Wo + bo + dng)
    bgemm<3, true><<<dim3(32, 32), 256, GEMM_SMEM>>>(
        aohi, aolo, Wohi, Wolo, out, dng, bo, nullptr, nullptr,
        NN, NN, DM, DM, NN, 0, 0, 0, 0, 1.f);
}

// round 11
// speedup vs baseline: 1.0359x; 1.0359x over previous
#include <cuda_runtime.h>
#include <cuda_bf16.h>
#include <cstdint>

#define NN 4096
#define DM 1024
#define KW 10
#define NQKV 3072
#define MAXNNZ 256

typedef __nv_bfloat16 bf16;

// ---------------------------------------------------------------------------
// Scratch (device globals; allocation-free)
// ---------------------------------------------------------------------------
__device__ __align__(256) float g_dng   [(size_t)NN*NN];
__device__ __align__(256) float g_scores[(size_t)NN*NN];
__device__ __align__(256) float g_P     [(size_t)KW*NN*DM];
__device__ __align__(256) float g_Kf    [(size_t)NN*DM];
__device__ __align__(256) float g_bcat  [NQKV];
__device__ __align__(256) float g_row[NN];
__device__ __align__(256) float g_col[NN];
__device__ __align__(256) int   g_nnzidx[(size_t)NN*MAXNNZ];
__device__ __align__(256) int   g_nnzcnt[NN];

__device__ __align__(256) bf16 g_Shi [(size_t)NN*NN];
__device__ __align__(256) bf16 g_Slo [(size_t)NN*NN];
__device__ __align__(256) bf16 g_xhi [(size_t)NN*NN];
__device__ __align__(256) bf16 g_xlo [(size_t)NN*NN];
__device__ __align__(256) bf16 g_athi[(size_t)NN*NN];
__device__ __align__(256) bf16 g_atlo[(size_t)NN*NN];
__device__ __align__(256) bf16 g_Wshi[(size_t)KW*NN*DM];
__device__ __align__(256) bf16 g_Wslo[(size_t)KW*NN*DM];
__device__ __align__(256) bf16 g_hhi [(size_t)NN*DM];
__device__ __align__(256) bf16 g_hlo [(size_t)NN*DM];
__device__ __align__(256) bf16 g_QKVhi[(size_t)NN*NQKV];  // [Q|K|V] split (K block unused)
__device__ __align__(256) bf16 g_QKVlo[(size_t)NN*NQKV];
__device__ __align__(256) bf16 g_KThi[(size_t)DM*NN];     // K^T split
__device__ __align__(256) bf16 g_KTlo[(size_t)DM*NN];
__device__ __align__(256) bf16 g_aohi[(size_t)NN*DM];
__device__ __align__(256) bf16 g_aolo[(size_t)NN*DM];
__device__ __align__(256) bf16 g_Wcathi[(size_t)DM*NQKV]; // [Wq|Wk|Wv] split
__device__ __align__(256) bf16 g_Wcatlo[(size_t)DM*NQKV];
__device__ __align__(256) bf16 g_Wohi[(size_t)DM*NN];
__device__ __align__(256) bf16 g_Wolo[(size_t)DM*NN];

// ---------------------------------------------------------------------------
// Streams / events (static init; pre-checkpoint)
// ---------------------------------------------------------------------------
static cudaStream_t g_s2 = nullptr;
static cudaEvent_t  g_evF = nullptr, g_evJ = nullptr;
static struct _AsyncInit {
    _AsyncInit() {
        if (cudaStreamCreateWithFlags(&g_s2, cudaStreamNonBlocking) != cudaSuccess) g_s2 = nullptr;
        if (cudaEventCreateWithFlags(&g_evF, cudaEventDisableTiming) != cudaSuccess) g_evF = nullptr;
        if (cudaEventCreateWithFlags(&g_evJ, cudaEventDisableTiming) != cudaSuccess) g_evJ = nullptr;
    }
} g_asyncInit;

// ---------------------------------------------------------------------------
// PTX helpers
// ---------------------------------------------------------------------------
__device__ __forceinline__ void cp16_s(uint32_t s, const void* g) {
    asm volatile("cp.async.cg.shared.global [%0], [%1], 16;\n" :: "r"(s), "l"(g));
}
__device__ __forceinline__ void cp_commit() { asm volatile("cp.async.commit_group;\n"); }
template<int W> __device__ __forceinline__ void cp_wait() {
    asm volatile("cp.async.wait_group %0;\n" :: "n"(W));
}
__device__ __forceinline__ void ldsm4(uint32_t& r0, uint32_t& r1, uint32_t& r2, uint32_t& r3,
                                      uint32_t addr) {
    asm volatile("ldmatrix.sync.aligned.m8n8.x4.shared.b16 {%0,%1,%2,%3}, [%4];\n"
                 : "=r"(r0), "=r"(r1), "=r"(r2), "=r"(r3) : "r"(addr));
}
__device__ __forceinline__ void ldsm4t(uint32_t& r0, uint32_t& r1, uint32_t& r2, uint32_t& r3,
                                       uint32_t addr) {
    asm volatile("ldmatrix.sync.aligned.m8n8.x4.trans.shared.b16 {%0,%1,%2,%3}, [%4];\n"
                 : "=r"(r0), "=r"(r1), "=r"(r2), "=r"(r3) : "r"(addr));
}
__device__ __forceinline__ void mma16816(float* c, const uint32_t* a, const uint32_t* b) {
    asm volatile("mma.sync.aligned.m16n8k16.row.col.f32.bf16.bf16.f32 "
                 "{%0,%1,%2,%3}, {%4,%5,%6,%7}, {%8,%9}, {%0,%1,%2,%3};\n"
                 : "+f"(c[0]), "+f"(c[1]), "+f"(c[2]), "+f"(c[3])
                 : "r"(a[0]), "r"(a[1]), "r"(a[2]), "r"(a[3]), "r"(b[0]), "r"(b[1]));
}

__device__ __forceinline__ void split2_store(bf16* hi, bf16* lo, size_t idx, float2 v) {
    bf16 hx = __float2bfloat16(v.x), hy = __float2bfloat16(v.y);
    bf16 lx = __float2bfloat16(v.x - __bfloat162float(hx));
    bf16 ly = __float2bfloat16(v.y - __bfloat162float(hy));
    *(__nv_bfloat162*)&hi[idx] = __halves2bfloat162(hx, hy);
    *(__nv_bfloat162*)&lo[idx] = __halves2bfloat162(lx, ly);
}

// ---------------------------------------------------------------------------
// bf16 split GEMM (tensor cores): 128x128 tile, K-chunk 32, 256 threads,
// 3-stage cp.async pipeline, 2 CTAs/SM (regs<=128 via launch_bounds and
// sequential split-fragment passes: a0b0, a0b1, a1b0 with a1 overwriting a0).
// Compensated product: Ah@Bh + Ah@Bl + Al@Bh (SPLIT) else Ah@Bh.
// EPI 0: C=acc ; 2: C=alpha*acc+D ; 3: C=relu(acc+bias+D)
// EPI 4: t=acc+bias; cols[1024,2048) fp32->C only (ld DM); others split->OHi/OLo (ldo)
// EPI 5: split-store acc -> OHi/OLo (ldo)
// ---------------------------------------------------------------------------
#define A_TILE_B 10240          // 128 rows * 80B (64B data + 16B pad)
#define B_TILE_B 8192           // 32 rows * 256B, xor swizzled
#define STAGE_B  (2*A_TILE_B + 2*B_TILE_B)   // 36864
#define STAGES   3
#define GEMM_SMEM (STAGES * STAGE_B)         // 110592 -> 2 CTAs/SM

template<int EPI, bool SPLIT>
__global__ void __launch_bounds__(256, 2)
bgemm(const bf16* __restrict__ Ah, const bf16* __restrict__ Al,
      const bf16* __restrict__ Bh, const bf16* __restrict__ Bl,
      float* __restrict__ C, const float* __restrict__ D,
      const float* __restrict__ bias,
      bf16* __restrict__ OHi, bf16* __restrict__ OLo,
      int M, int N, int K, int lda, int ldb, int ldo,
      size_t aSz, size_t bSz, size_t cSz, float alpha)
{
    extern __shared__ char smem[];

    const int t    = threadIdx.x;
    const int lane = t & 31;
    const int wid  = t >> 5;
    const int m0   = blockIdx.y * 128;
    const int n0   = blockIdx.x * 128;
    const int z    = blockIdx.z;

    const bf16* Ahp = Ah + (size_t)z * aSz;
    const bf16* Alp = SPLIT ? (Al + (size_t)z * aSz) : nullptr;
    const bf16* Bhp = Bh + (size_t)z * bSz;
    const bf16* Blp = SPLIT ? (Bl + (size_t)z * bSz) : nullptr;
    float*      Cp  = C ? (C + (size_t)z * cSz) : nullptr;

    const int m0w = (wid & 1) * 64;
    const int n0w = (wid >> 1) * 32;

    const uint32_t smemU = (uint32_t)__cvta_generic_to_shared(smem);

    float acc[4][4][4] = {};
    const int nch = K >> 5;   // K / 32

    const int ar0 = t >> 2, ac0 = t & 3;   // A: 2 iters of (row += 64)
    const int br0 = t >> 4, bc0 = t & 15;  // B: 2 iters of (row += 16)

    auto load_stage = [&](int buf, int kc) {
        const int kg = kc << 5;
        const uint32_t sb = smemU + buf * STAGE_B;
#pragma unroll
        for (int i = 0; i < 2; i++) {
            int r = ar0 + i * 64, c = ac0;
            uint32_t dst = sb + r * 80 + c * 16;
            cp16_s(dst, Ahp + (size_t)(m0 + r) * lda + kg + c * 8);
            if (SPLIT)
                cp16_s(dst + A_TILE_B, Alp + (size_t)(m0 + r) * lda + kg + c * 8);
        }
#pragma unroll
        for (int i = 0; i < 2; i++) {
            int r = br0 + i * 16, c = bc0;
            uint32_t dst = sb + 2 * A_TILE_B + r * 256 + ((c ^ (r & 7)) * 16);
            cp16_s(dst, Bhp + (size_t)(kg + r) * ldb + n0 + c * 8);
            if (SPLIT)
                cp16_s(dst + B_TILE_B, Blp + (size_t)(kg + r) * ldb + n0 + c * 8);
        }
    };

    auto compute_stage = [&](int buf) {
        const uint32_t sb = smemU + buf * STAGE_B;
        const uint32_t aBase = sb + (m0w + (lane & 15)) * 80 + (lane >> 4) * 16;
        const int krow0 = lane & 15;
        const int chAdd = (n0w >> 3) + (lane >> 4);
#pragma unroll
        for (int ks = 0; ks < 2; ks++) {
            uint32_t a[4][4];
            uint32_t b0[4][2], b1[4][2];
            const int krow = ks * 16 + krow0;
            // --- a0 (hi) + b0 (hi): main product ---
#pragma unroll
            for (int mt = 0; mt < 4; mt++) {
                uint32_t addr = aBase + mt * (16 * 80) + ks * 32;
                ldsm4(a[mt][0], a[mt][1], a[mt][2], a[mt][3], addr);
            }
#pragma unroll
            for (int nt = 0; nt < 2; nt++) {
                int ch = (chAdd + nt * 2) ^ (krow & 7);
                uint32_t addr = sb + 2 * A_TILE_B + krow * 256 + ch * 16;
                uint32_t r0, r1, r2, r3;
                ldsm4t(r0, r1, r2, r3, addr);
                b0[nt * 2][0] = r0;  b0[nt * 2][1] = r1;
                b0[nt * 2 + 1][0] = r2;  b0[nt * 2 + 1][1] = r3;
            }
#pragma unroll
            for (int mt = 0; mt < 4; mt++)
#pragma unroll
                for (int nj = 0; nj < 4; nj++)
                    mma16816(acc[mt][nj], a[mt], b0[nj]);

            if (SPLIT) {
                // --- a0 (hi) x b1 (lo) ---
#pragma unroll
                for (int nt = 0; nt < 2; nt++) {
                    int ch = (chAdd + nt * 2) ^ (krow & 7);
                    uint32_t addr = sb + 2 * A_TILE_B + B_TILE_B + krow * 256 + ch * 16;
                    uint32_t r0, r1, r2, r3;
                    ldsm4t(r0, r1, r2, r3, addr);
                    b1[nt * 2][0] = r0;  b1[nt * 2][1] = r1;
                    b1[nt * 2 + 1][0] = r2;  b1[nt * 2 + 1][1] = r3;
                }
#pragma unroll
                for (int mt = 0; mt < 4; mt++)
#pragma unroll
                    for (int nj = 0; nj < 4; nj++)
                        mma16816(acc[mt][nj], a[mt], b1[nj]);
                // --- a1 (lo, overwrites a) x b0 (hi) ---
#pragma unroll
                for (int mt = 0; mt < 4; mt++) {
                    uint32_t addr = aBase + A_TILE_B + mt * (16 * 80) + ks * 32;
                    ldsm4(a[mt][0], a[mt][1], a[mt][2], a[mt][3], addr);
                }
#pragma unroll
                for (int mt = 0; mt < 4; mt++)
#pragma unroll
                    for (int nj = 0; nj < 4; nj++)
                        mma16816(acc[mt][nj], a[mt], b0[nj]);
            }
        }
    };

    load_stage(0, 0); cp_commit();
    load_stage(1, 1); cp_commit();
    cp_wait<1>();
    __syncthreads();

    for (int i = 0; i < nch; i++) {
        if (i + 2 < nch) load_stage((i + 2) % STAGES, i + 2);
        cp_commit();
        compute_stage(i % STAGES);
        cp_wait<1>();
        __syncthreads();
    }

    // epilogue
#pragma unroll
    for (int mt = 0; mt < 4; mt++) {
        int r0 = m0 + m0w + mt * 16 + (lane >> 2);
        int r1 = r0 + 8;
#pragma unroll
        for (int nj = 0; nj < 4; nj++) {
            int c = n0 + n0w + nj * 8 + (lane & 3) * 2;
            float2 v0 = make_float2(acc[mt][nj][0], acc[mt][nj][1]);
            float2 v1 = make_float2(acc[mt][nj][2], acc[mt][nj][3]);
            if (EPI == 3 || EPI == 4) {
                float2 bz = *(const float2*)&bias[c];
                v0.x += bz.x; v0.y += bz.y;
                v1.x += bz.x; v1.y += bz.y;
            }
            if (EPI == 2) {
                float2 d0 = *(const float2*)&D[(size_t)r0 * N + c];
                float2 d1 = *(const float2*)&D[(size_t)r1 * N + c];
                v0.x = fmaf(v0.x, alpha, d0.x); v0.y = fmaf(v0.y, alpha, d0.y);
                v1.x = fmaf(v1.x, alpha, d1.x); v1.y = fmaf(v1.y, alpha, d1.y);
            }
            if (EPI == 3) {
                float2 d0 = *(const float2*)&D[(size_t)r0 * N + c];
                float2 d1 = *(const float2*)&D[(size_t)r1 * N + c];
                v0.x = fmaxf(v0.x + d0.x, 0.f); v0.y = fmaxf(v0.y + d0.y, 0.f);
                v1.x = fmaxf(v1.x + d1.x, 0.f); v1.y = fmaxf(v1.y + d1.y, 0.f);
            }
            if (EPI == 4) {
                if (c >= DM && c < 2 * DM) {      // K block -> fp32 side store only
                    *(float2*)&C[(size_t)r0 * DM + (c - DM)] = v0;
                    *(float2*)&C[(size_t)r1 * DM + (c - DM)] = v1;
                } else {                          // Q and V blocks -> split store
                    split2_store(OHi, OLo, (size_t)r0 * ldo + c, v0);
                    split2_store(OHi, OLo, (size_t)r1 * ldo + c, v1);
                }
            } else if (EPI == 5) {
                split2_store(OHi, OLo, (size_t)r0 * ldo + c, v0);
                split2_store(OHi, OLo, (size_t)r1 * ldo + c, v1);
            } else {
                *(float2*)&Cp[(size_t)r0 * N + c] = v0;
                *(float2*)&Cp[(size_t)r1 * N + c] = v1;
            }
        }
    }
}

// ---------------------------------------------------------------------------
// Elementwise / conversion kernels
// ---------------------------------------------------------------------------
__device__ __forceinline__ void split4_store(bf16* hi, bf16* lo, size_t i4, float4 v) {
    bf16 hx = __float2bfloat16(v.x), hy = __float2bfloat16(v.y);
    bf16 hz = __float2bfloat16(v.z), hw = __float2bfloat16(v.w);
    bf16 lx = __float2bfloat16(v.x - __bfloat162float(hx));
    bf16 ly = __float2bfloat16(v.y - __bfloat162float(hy));
    bf16 lz = __float2bfloat16(v.z - __bfloat162float(hz));
    bf16 lw = __float2bfloat16(v.w - __bfloat162float(hw));
    ((__nv_bfloat162*)hi)[2 * i4]     = __halves2bfloat162(hx, hy);
    ((__nv_bfloat162*)hi)[2 * i4 + 1] = __halves2bfloat162(hz, hw);
    ((__nv_bfloat162*)lo)[2 * i4]     = __halves2bfloat162(lx, ly);
    ((__nv_bfloat162*)lo)[2 * i4 + 1] = __halves2bfloat162(lz, lw);
}

// 32B per thread (2 independent float4s)
__global__ void split_kernel(const float* __restrict__ src, bf16* __restrict__ hi,
                             bf16* __restrict__ lo)
{
    size_t g = (size_t)blockIdx.x * blockDim.x + threadIdx.x;
    float4 v0 = ((const float4*)src)[2 * g];
    float4 v1 = ((const float4*)src)[2 * g + 1];
    split4_store(hi, lo, 2 * g, v0);
    split4_store(hi, lo, 2 * g + 1, v1);
}

// column-concat [Wq|Wk|Wv] ([DM,DM] each) -> split [DM, 3072]; 2 i4 per thread
__global__ void catsplit3_kernel(const float* __restrict__ Wq, const float* __restrict__ Wk,
                                 const float* __restrict__ Wv,
                                 bf16* __restrict__ hi, bf16* __restrict__ lo)
{
    size_t g = (size_t)blockIdx.x * blockDim.x + threadIdx.x;
#pragma unroll
    for (int u = 0; u < 2; u++) {
        size_t i4 = 2 * g + u;
        int k  = (int)(i4 / (NQKV / 4));
        int nq = (int)(i4 % (NQKV / 4));
        const float* src = (nq < 256) ? &Wq[(size_t)k * DM + nq * 4]
                         : (nq < 512) ? &Wk[(size_t)k * DM + (nq - 256) * 4]
                                      : &Wv[(size_t)k * DM + (nq - 512) * 4];
        float4 v = *(const float4*)src;
        split4_store(hi, lo, i4, v);
    }
}

__global__ void bcat_kernel(const float* __restrict__ bq, const float* __restrict__ bk,
                            const float* __restrict__ bv, float* __restrict__ o)
{
    int i = blockIdx.x * 256 + threadIdx.x;
    if (i < NQKV)
        o[i] = (i < DM) ? bq[i] : (i < 2 * DM) ? bk[i - DM] : bv[i - 2 * DM];
}

// split + transpose: src [R,C] fp32 -> hiT/loT [C,R] bf16
__global__ void splitT_kernel(const float* __restrict__ src, bf16* __restrict__ hiT,
                              bf16* __restrict__ loT, int R, int Cc)
{
    __shared__ float tile[32][33];
    int c0 = blockIdx.x * 32, r0 = blockIdx.y * 32;
    int tx = threadIdx.x, ty = threadIdx.y;
    for (int i = ty; i < 32; i += 8)
        tile[i][tx] = src[(size_t)(r0 + i) * Cc + c0 + tx];
    __syncthreads();
    for (int i = ty; i < 32; i += 8) {
        float v = tile[tx][i];
        bf16 h = __float2bfloat16(v);
        bf16 l = __float2bfloat16(v - __bfloat162float(h));
        size_t o = (size_t)(c0 + i) * R + r0 + tx;
        hiT[o] = h; loT[o] = l;
    }
}

__global__ void zero_kernel(float* __restrict__ p, int n)
{
    int i = blockIdx.x * blockDim.x + threadIdx.x;
    if (i < n) p[i] = 0.f;
}

__global__ void rowsum_kernel(const float* __restrict__ A, float* __restrict__ rowv)
{
    int warp = threadIdx.x >> 5, lane = threadIdx.x & 31;
    int row = blockIdx.x * 8 + warp;
    const float4* p = (const float4*)(A + (size_t)row * NN);
    float s = 0.f;
#pragma unroll
    for (int i = 0; i < 32; i++) {
        float4 v = p[lane + i * 32];
        s += v.x + v.y + v.z + v.w;
    }
#pragma unroll
    for (int o = 16; o; o >>= 1) s += __shfl_down_sync(0xffffffffu, s, o);
    if (!lane) rowv[row] = s;
}

__global__ void colsum_kernel(const float* __restrict__ A, float* __restrict__ colv)
{
    int j = blockIdx.x * 256 + threadIdx.x;
    int i0 = blockIdx.y * 256;
    float s = 0.f;
    for (int i = 0; i < 256; i++) s += A[(size_t)(i0 + i) * NN + j];
    atomicAdd(&colv[j], s);
}

__global__ void build_nnz_kernel(const float* __restrict__ A, int* __restrict__ idx,
                                 int* __restrict__ cnt)
{
    int row = blockIdx.x;
    __shared__ int c;
    if (threadIdx.x == 0) c = 0;
    __syncthreads();
    for (int col = threadIdx.x; col < NN; col += 256) {
        if (A[(size_t)row * NN + col] != 0.f) {
            int p = atomicAdd(&c, 1);
            if (p < MAXNNZ) idx[(size_t)row * MAXNNZ + p] = col;
        }
    }
    __syncthreads();
    if (threadIdx.x == 0) cnt[row] = (c < MAXNNZ) ? c : MAXNNZ;
}

// sparse inter + simfuse fused
__global__ void __launch_bounds__(256)
simfuse_sparse_kernel(const float* __restrict__ A, const float* __restrict__ G,
                      const int* __restrict__ idx, const int* __restrict__ cnt,
                      const float* __restrict__ rowv, const float* __restrict__ colv,
                      bf16* __restrict__ Shi, bf16* __restrict__ Slo)
{
    const int row = blockIdx.x;
    const int t = threadIdx.x;

    __shared__ int sidx[MAXNNZ];
    const int n = cnt[row];
    for (int e = t; e < n; e += 256) sidx[e] = idx[(size_t)row * MAXNNZ + e];
    __syncthreads();

    float4 acc[4] = {};
    for (int e = 0; e < n; e++) {
        const float4* Aj = (const float4*)(A + (size_t)sidx[e] * NN);
#pragma unroll
        for (int m = 0; m < 4; m++) {
            float4 v = Aj[t + m * 256];
            acc[m].x += v.x; acc[m].y += v.y; acc[m].z += v.z; acc[m].w += v.w;
        }
    }

    const float r = rowv[row];
    const float4* Ai = (const float4*)(A + (size_t)row * NN);
    const float4* Gi = (const float4*)(G + (size_t)row * NN);
    bf16* hi = Shi + (size_t)row * NN;
    bf16* lo = Slo + (size_t)row * NN;
#pragma unroll
    for (int m = 0; m < 4; m++) {
        int f4 = t + m * 256;
        float4 v = acc[m];
        float4 a = Ai[f4];
        float4 g = Gi[f4];
        float4 c = *(const float4*)&colv[f4 * 4];
        float4 o;
        o.x = v.x / (r + c.x - v.x + 1e-6f) + a.x + g.x;
        o.y = v.y / (r + c.y - v.y + 1e-6f) + a.y + g.y;
        o.z = v.z / (r + c.z - v.z + 1e-6f) + a.z + g.z;
        o.w = v.w / (r + c.w - v.w + 1e-6f) + a.w + g.w;
        split4_store(hi, lo, (size_t)f4, o);
    }
}

__global__ void combine_ln_kernel(const float* __restrict__ P, const float* __restrict__ w,
                                  const float* __restrict__ bstk,
                                  const float* __restrict__ gamma, const float* __restrict__ beta,
                                  bf16* __restrict__ hhi, bf16* __restrict__ hlo)
{
    int n = blockIdx.x, t = threadIdx.x;
    float wn[KW];
#pragma unroll
    for (int k = 0; k < KW; k++) wn[k] = w[n * KW + k];
    float4 v = make_float4(0.f, 0.f, 0.f, 0.f);
#pragma unroll
    for (int k = 0; k < KW; k++) {
        float4 p = ((const float4*)(P + ((size_t)k * NN + n) * DM))[t];
        float4 b = ((const float4*)(bstk + (size_t)k * DM))[t];
        v.x = fmaf(wn[k], p.x + b.x, v.x);
        v.y = fmaf(wn[k], p.y + b.y, v.y);
        v.z = fmaf(wn[k], p.z + b.z, v.z);
        v.w = fmaf(wn[k], p.w + b.w, v.w);
    }
    float s  = v.x + v.y + v.z + v.w;
    float s2 = v.x * v.x + v.y * v.y + v.z * v.z + v.w * v.w;
    __shared__ float sS[8], sS2[8], sMean, sInv;
    int warp = t >> 5, lane = t & 31;
#pragma unroll
    for (int o = 16; o; o >>= 1) {
        s  += __shfl_down_sync(0xffffffffu, s, o);
        s2 += __shfl_down_sync(0xffffffffu, s2, o);
    }
    if (!lane) { sS[warp] = s; sS2[warp] = s2; }
    __syncthreads();
    if (t == 0) {
        float S = 0.f, S2 = 0.f;
        for (int i = 0; i < 8; i++) { S += sS[i]; S2 += sS2[i]; }
        float mean = S * (1.f / DM);
        float var  = S2 * (1.f / DM) - mean * mean;
        sMean = mean;
        sInv  = rsqrtf(var + 1e-5f);
    }
    __syncthreads();
    float mean = sMean, inv = sInv;
    float4 gg = ((const float4*)gamma)[t];
    float4 bb = ((const float4*)beta)[t];
    float4 o;
    o.x = (v.x - mean) * inv * gg.x + bb.x;
    o.y = (v.y - mean) * inv * gg.y + bb.y;
    o.z = (v.z - mean) * inv * gg.z + bb.z;
    o.w = (v.w - mean) * inv * gg.w + bb.w;
    split4_store(hhi + (size_t)n * DM, hlo + (size_t)n * DM, t, o);
}

__global__ void softmax_kernel(const float* __restrict__ S, bf16* __restrict__ Ohi,
                               bf16* __restrict__ Olo)
{
    int r = blockIdx.x, t = threadIdx.x;
    const float4* row = (const float4*)(S + (size_t)r * NN);
    float4 v[4];
    float mx = -1e30f;
#pragma unroll
    for (int i = 0; i < 4; i++) {
        v[i] = row[t + i * 256];
        mx = fmaxf(mx, fmaxf(fmaxf(v[i].x, v[i].y), fmaxf(v[i].z, v[i].w)));
    }
    __shared__ float sh[8];
    __shared__ float sbc;
    int warp = t >> 5, lane = t & 31;
#pragma unroll
    for (int o = 16; o; o >>= 1) mx = fmaxf(mx, __shfl_xor_sync(0xffffffffu, mx, o));
    if (!lane) sh[warp] = mx;
    __syncthreads();
    if (t == 0) {
        float m = sh[0];
        for (int i = 1; i < 8; i++) m = fmaxf(m, sh[i]);
        sbc = m;
    }
    __syncthreads();
    mx = sbc;
    float s = 0.f;
#pragma unroll
    for (int i = 0; i < 4; i++) {
        v[i].x = __expf(v[i].x - mx);
        v[i].y = __expf(v[i].y - mx);
        v[i].z = __expf(v[i].z - mx);
        v[i].w = __expf(v[i].w - mx);
        s += v[i].x + v[i].y + v[i].z + v[i].w;
    }
#pragma unroll
    for (int o = 16; o; o >>= 1) s += __shfl_xor_sync(0xffffffffu, s, o);
    __syncthreads();
    if (!lane) sh[warp] = s;
    __syncthreads();
    if (t == 0) {
        float z = 0.f;
        for (int i = 0; i < 8; i++) z += sh[i];
        sbc = 1.f / z;
    }
    __syncthreads();
    float inv = sbc;
    bf16* hi = Ohi + (size_t)r * NN;
    bf16* lo = Olo + (size_t)r * NN;
#pragma unroll
    for (int i = 0; i < 4; i++) {
        float4 o;
        o.x = v[i].x * inv; o.y = v[i].y * inv; o.z = v[i].z * inv; o.w = v[i].w * inv;
        split4_store(hi, lo, (size_t)(t + i * 256), o);
    }
}

// ---------------------------------------------------------------------------
// Host launcher
// ---------------------------------------------------------------------------
extern "C" void kernel_launch(void* const* d_in, const int* in_sizes, int n_in,
                              void* d_out, int out_size)
{
    const float* x     = (const float*)d_in[0];
    const float* A     = (const float*)d_in[1];
    const float* G     = (const float*)d_in[2];
    const float* w     = (const float*)d_in[3];
    const float* Wstk  = (const float*)d_in[4];
    const float* bstk  = (const float*)d_in[5];
    const float* Wq    = (const float*)d_in[6];
    const float* bq    = (const float*)d_in[7];
    const float* Wk    = (const float*)d_in[8];
    const float* bk    = (const float*)d_in[9];
    const float* Wv    = (const float*)d_in[10];
    const float* bv    = (const float*)d_in[11];
    const float* Wo    = (const float*)d_in[12];
    const float* bo    = (const float*)d_in[13];
    const float* gamma = (const float*)d_in[14];
    const float* beta  = (const float*)d_in[15];
    float* out = (float*)d_out;

    float *dng, *scores, *P, *Kf, *bcat, *rowv, *colv;
    int *nnzidx, *nnzcnt;
    bf16 *Shi, *Slo, *xhi, *xlo, *athi, *atlo, *Wshi, *Wslo, *hhi, *hlo;
    bf16 *QKVhi, *QKVlo, *KThi, *KTlo, *aohi, *aolo, *Wcathi, *Wcatlo, *Wohi, *Wolo;
    cudaGetSymbolAddress((void**)&dng, g_dng);
    cudaGetSymbolAddress((void**)&scores, g_scores);
    cudaGetSymbolAddress((void**)&P, g_P);
    cudaGetSymbolAddress((void**)&Kf, g_Kf);
    cudaGetSymbolAddress((void**)&bcat, g_bcat);
    cudaGetSymbolAddress((void**)&rowv, g_row);
    cudaGetSymbolAddress((void**)&colv, g_col);
    cudaGetSymbolAddress((void**)&nnzidx, g_nnzidx);
    cudaGetSymbolAddress((void**)&nnzcnt, g_nnzcnt);
    cudaGetSymbolAddress((void**)&Shi, g_Shi);
    cudaGetSymbolAddress((void**)&Slo, g_Slo);
    cudaGetSymbolAddress((void**)&xhi, g_xhi);
    cudaGetSymbolAddress((void**)&xlo, g_xlo);
    cudaGetSymbolAddress((void**)&athi, g_athi);
    cudaGetSymbolAddress((void**)&atlo, g_atlo);
    cudaGetSymbolAddress((void**)&Wshi, g_Wshi);
    cudaGetSymbolAddress((void**)&Wslo, g_Wslo);
    cudaGetSymbolAddress((void**)&hhi, g_hhi);
    cudaGetSymbolAddress((void**)&hlo, g_hlo);
    cudaGetSymbolAddress((void**)&QKVhi, g_QKVhi);
    cudaGetSymbolAddress((void**)&QKVlo, g_QKVlo);
    cudaGetSymbolAddress((void**)&KThi, g_KThi);
    cudaGetSymbolAddress((void**)&KTlo, g_KTlo);
    cudaGetSymbolAddress((void**)&aohi, g_aohi);
    cudaGetSymbolAddress((void**)&aolo, g_aolo);
    cudaGetSymbolAddress((void**)&Wcathi, g_Wcathi);
    cudaGetSymbolAddress((void**)&Wcatlo, g_Wcatlo);
    cudaGetSymbolAddress((void**)&Wohi, g_Wohi);
    cudaGetSymbolAddress((void**)&Wolo, g_Wolo);

    cudaFuncSetAttribute(bgemm<0, true>,  cudaFuncAttributeMaxDynamicSharedMemorySize, GEMM_SMEM);
    cudaFuncSetAttribute(bgemm<2, true>,  cudaFuncAttributeMaxDynamicSharedMemorySize, GEMM_SMEM);
    cudaFuncSetAttribute(bgemm<3, true>,  cudaFuncAttributeMaxDynamicSharedMemorySize, GEMM_SMEM);
    cudaFuncSetAttribute(bgemm<4, true>,  cudaFuncAttributeMaxDynamicSharedMemorySize, GEMM_SMEM);
    cudaFuncSetAttribute(bgemm<5, true>,  cudaFuncAttributeMaxDynamicSharedMemorySize, GEMM_SMEM);

    const size_t NDM = (size_t)NN * DM;
    const bool fork = (g_s2 != nullptr) && (g_evF != nullptr) && (g_evJ != nullptr);
    cudaStream_t sB = fork ? g_s2 : (cudaStream_t)0;
    dim3 tb(32, 8);

    // ---- pre-fork (stream 0): x split (both chains need it) ----
    split_kernel<<<NN * (NN / 4) / 512, 256>>>(x, xhi, xlo);

    if (fork) {
        cudaEventRecord(g_evF, 0);
        cudaStreamWaitEvent(sB, g_evF, 0);
    }

    // ======================= chain B (stream sB) =======================
    // W_stack split gates P — run it first, launch P immediately after.
    split_kernel<<<(int)(KW * NDM / 4 / 512), 256, 0, sB>>>(Wstk, Wshi, Wslo);

    // P_k = x @ W_k (batched)
    bgemm<0, true><<<dim3(8, 32, KW), 256, GEMM_SMEM, sB>>>(
        xhi, xlo, Wshi, Wslo, P, nullptr, nullptr, nullptr, nullptr,
        NN, DM, NN, NN, DM, 0, 0, NDM, NDM, 1.f);

    // conversions that only gate the (much later) QKV / out GEMMs
    catsplit3_kernel<<<DM * (NQKV / 4) / 512, 256, 0, sB>>>(Wq, Wk, Wv, Wcathi, Wcatlo);
    bcat_kernel<<<12, 256, 0, sB>>>(bq, bk, bv, bcat);
    split_kernel<<<DM * (NN / 4) / 512, 256, 0, sB>>>(Wo, Wohi, Wolo);

    combine_ln_kernel<<<NN, 256, 0, sB>>>(P, w, bstk, gamma, beta, hhi, hlo);

    // fused [Q|K|V] = h @ [Wq|Wk|Wv] + bcat; Q/V split stores + K fp32 side store
    bgemm<4, true><<<dim3(NQKV / 128, 32), 256, GEMM_SMEM, sB>>>(
        hhi, hlo, Wcathi, Wcatlo, Kf, nullptr, bcat, QKVhi, QKVlo,
        NN, NQKV, DM, DM, NQKV, NQKV, 0, 0, 0, 1.f);

    splitT_kernel<<<dim3(DM / 32, NN / 32), tb, 0, sB>>>(Kf, KThi, KTlo, NN, DM);

    if (fork) cudaEventRecord(g_evJ, sB);

    // ======================= chain A (stream 0) =======================
    zero_kernel<<<16, 256>>>(colv, NN);
    build_nnz_kernel<<<NN, 256>>>(A, nnzidx, nnzcnt);
    rowsum_kernel<<<NN / 8, 256>>>(A, rowv);
    colsum_kernel<<<dim3(16, 16), 256>>>(A, colv);

    // sparse inter=A@A + simfuse -> S split
    simfuse_sparse_kernel<<<NN, 256>>>(A, G, nnzidx, nnzcnt, rowv, colv, Shi, Slo);

    // dng = S @ x
    bgemm<0, true><<<dim3(32, 32), 256, GEMM_SMEM>>>(
        Shi, Slo, xhi, xlo, dng, nullptr, nullptr, nullptr, nullptr,
        NN, NN, NN, NN, NN, 0, 0, 0, 0, 1.f);

    // ======================= join =======================
    if (fork) cudaStreamWaitEvent(0, g_evJ, 0);

    // scores = Q @ K^T / 32 + dng
    bgemm<2, true><<<dim3(32, 32), 256, GEMM_SMEM>>>(
        QKVhi, QKVlo, KThi, KTlo, scores, dng, nullptr, nullptr, nullptr,
        NN, NN, DM, NQKV, NN, 0, 0, 0, 0, 0.03125f);

    softmax_kernel<<<NN, 256>>>(scores, athi, atlo);

    // ao = attn @ V  (V = QKV cols [2048,3072)); split-store ao
    bgemm<5, true><<<dim3(8, 32), 256, GEMM_SMEM>>>(
        athi, atlo, QKVhi + 2 * DM, QKVlo + 2 * DM, nullptr, nullptr, nullptr, aohi, aolo,
        NN, DM, NN, NN, NQKV, DM, 0, 0, 0, 1.f);

    // out = relu(ao @ Wo + bo + dng)
    bgemm<3, true><<<dim3(32, 32), 256, GEMM_SMEM>>>(
        aohi, aolo, Wohi, Wolo, out, dng, bo, nullptr, nullptr,
        NN, NN, DM, DM, NN, 0, 0, 0, 0, 1.f);
}

// round 12
// speedup vs baseline: 1.0531x; 1.0167x over previous
#include <cuda_runtime.h>
#include <cuda_bf16.h>
#include <cstdint>

#define NN 4096
#define DM 1024
#define KW 10
#define MAXNNZ 256

typedef __nv_bfloat16 bf16;

// ---------------------------------------------------------------------------
// Scratch (device globals; allocation-free)
// ---------------------------------------------------------------------------
__device__ __align__(256) float g_dng   [(size_t)NN*NN];
__device__ __align__(256) float g_scores[(size_t)NN*NN];
__device__ __align__(256) float g_P     [(size_t)KW*NN*DM];
__device__ __align__(256) float g_wkbq  [DM];
__device__ __align__(256) float g_cbs   [NN];
__device__ __align__(256) float g_row[NN];
__device__ __align__(256) float g_col[NN];
__device__ __align__(256) int   g_nnzidx[(size_t)NN*MAXNNZ];
__device__ __align__(256) int   g_nnzcnt[NN];

__device__ __align__(256) bf16 g_Shi [(size_t)NN*NN];
__device__ __align__(256) bf16 g_Slo [(size_t)NN*NN];
__device__ __align__(256) bf16 g_xhi [(size_t)NN*NN];
__device__ __align__(256) bf16 g_xlo [(size_t)NN*NN];
__device__ __align__(256) bf16 g_athi[(size_t)NN*NN];
__device__ __align__(256) bf16 g_atlo[(size_t)NN*NN];
__device__ __align__(256) bf16 g_Wshi[(size_t)KW*NN*DM];
__device__ __align__(256) bf16 g_Wslo[(size_t)KW*NN*DM];
__device__ __align__(256) bf16 g_hhi [(size_t)NN*DM];
__device__ __align__(256) bf16 g_hlo [(size_t)NN*DM];
__device__ __align__(256) bf16 g_hThi[(size_t)DM*NN];   // h^T split
__device__ __align__(256) bf16 g_hTlo[(size_t)DM*NN];
__device__ __align__(256) bf16 g_G1hi[(size_t)NN*DM];   // G1 = h @ M
__device__ __align__(256) bf16 g_G1lo[(size_t)NN*DM];
__device__ __align__(256) bf16 g_Vhi [(size_t)NN*DM];
__device__ __align__(256) bf16 g_Vlo [(size_t)NN*DM];
__device__ __align__(256) bf16 g_aohi[(size_t)NN*DM];
__device__ __align__(256) bf16 g_aolo[(size_t)NN*DM];
__device__ __align__(256) bf16 g_Wqhi[(size_t)DM*DM];
__device__ __align__(256) bf16 g_Wqlo[(size_t)DM*DM];
__device__ __align__(256) bf16 g_WkThi[(size_t)DM*DM];  // Wk^T split
__device__ __align__(256) bf16 g_WkTlo[(size_t)DM*DM];
__device__ __align__(256) bf16 g_Wvhi[(size_t)DM*DM];
__device__ __align__(256) bf16 g_Wvlo[(size_t)DM*DM];
__device__ __align__(256) bf16 g_Mhi [(size_t)DM*DM];   // M = Wq @ Wk^T
__device__ __align__(256) bf16 g_Mlo [(size_t)DM*DM];
__device__ __align__(256) bf16 g_Wohi[(size_t)DM*NN];
__device__ __align__(256) bf16 g_Wolo[(size_t)DM*NN];

// ---------------------------------------------------------------------------
// Streams / events (static init; pre-checkpoint)
// ---------------------------------------------------------------------------
static cudaStream_t g_s2 = nullptr;
static cudaEvent_t  g_evF = nullptr, g_evJ = nullptr, g_evM = nullptr;
static struct _AsyncInit {
    _AsyncInit() {
        if (cudaStreamCreateWithFlags(&g_s2, cudaStreamNonBlocking) != cudaSuccess) g_s2 = nullptr;
        if (cudaEventCreateWithFlags(&g_evF, cudaEventDisableTiming) != cudaSuccess) g_evF = nullptr;
        if (cudaEventCreateWithFlags(&g_evJ, cudaEventDisableTiming) != cudaSuccess) g_evJ = nullptr;
        if (cudaEventCreateWithFlags(&g_evM, cudaEventDisableTiming) != cudaSuccess) g_evM = nullptr;
    }
} g_asyncInit;

// ---------------------------------------------------------------------------
// PTX helpers
// ---------------------------------------------------------------------------
__device__ __forceinline__ void cp16_s(uint32_t s, const void* g) {
    asm volatile("cp.async.cg.shared.global [%0], [%1], 16;\n" :: "r"(s), "l"(g));
}
__device__ __forceinline__ void cp_commit() { asm volatile("cp.async.commit_group;\n"); }
template<int W> __device__ __forceinline__ void cp_wait() {
    asm volatile("cp.async.wait_group %0;\n" :: "n"(W));
}
__device__ __forceinline__ void ldsm4(uint32_t& r0, uint32_t& r1, uint32_t& r2, uint32_t& r3,
                                      uint32_t addr) {
    asm volatile("ldmatrix.sync.aligned.m8n8.x4.shared.b16 {%0,%1,%2,%3}, [%4];\n"
                 : "=r"(r0), "=r"(r1), "=r"(r2), "=r"(r3) : "r"(addr));
}
__device__ __forceinline__ void ldsm4t(uint32_t& r0, uint32_t& r1, uint32_t& r2, uint32_t& r3,
                                       uint32_t addr) {
    asm volatile("ldmatrix.sync.aligned.m8n8.x4.trans.shared.b16 {%0,%1,%2,%3}, [%4];\n"
                 : "=r"(r0), "=r"(r1), "=r"(r2), "=r"(r3) : "r"(addr));
}
__device__ __forceinline__ void mma16816(float* c, const uint32_t* a, const uint32_t* b) {
    asm volatile("mma.sync.aligned.m16n8k16.row.col.f32.bf16.bf16.f32 "
                 "{%0,%1,%2,%3}, {%4,%5,%6,%7}, {%8,%9}, {%0,%1,%2,%3};\n"
                 : "+f"(c[0]), "+f"(c[1]), "+f"(c[2]), "+f"(c[3])
                 : "r"(a[0]), "r"(a[1]), "r"(a[2]), "r"(a[3]), "r"(b[0]), "r"(b[1]));
}

__device__ __forceinline__ void split2_store(bf16* hi, bf16* lo, size_t idx, float2 v) {
    bf16 hx = __float2bfloat16(v.x), hy = __float2bfloat16(v.y);
    bf16 lx = __float2bfloat16(v.x - __bfloat162float(hx));
    bf16 ly = __float2bfloat16(v.y - __bfloat162float(hy));
    *(__nv_bfloat162*)&hi[idx] = __halves2bfloat162(hx, hy);
    *(__nv_bfloat162*)&lo[idx] = __halves2bfloat162(lx, ly);
}

// ---------------------------------------------------------------------------
// bf16 split GEMM: 128x128 tile, K-chunk 32, 256 threads, 3-stage cp.async,
// 2 CTAs/SM. Compensated: Ah@Bh + Ah@Bl + Al@Bh (SPLIT) else Ah@Bh.
// B is [K,N] row-major (ldb).
// EPI 0: C=acc
// EPI 3: C=relu(acc+bias+D)
// EPI 5: split-store acc -> OHi/OLo (ldo)
// EPI 6: split-store (acc+bias[col]) -> OHi/OLo (ldo)
// EPI 7: C = alpha*acc + D + bias[col]
// ---------------------------------------------------------------------------
#define A_TILE_B 10240
#define B_TILE_B 8192
#define STAGE_B  (2*A_TILE_B + 2*B_TILE_B)   // 36864
#define STAGES   3
#define GEMM_SMEM (STAGES * STAGE_B)         // 110592 -> 2 CTAs/SM

template<int EPI, bool SPLIT>
__global__ void __launch_bounds__(256, 2)
bgemm(const bf16* __restrict__ Ah, const bf16* __restrict__ Al,
      const bf16* __restrict__ Bh, const bf16* __restrict__ Bl,
      float* __restrict__ C, const float* __restrict__ D,
      const float* __restrict__ bias,
      bf16* __restrict__ OHi, bf16* __restrict__ OLo,
      int M, int N, int K, int lda, int ldb, int ldo,
      size_t aSz, size_t bSz, size_t cSz, float alpha)
{
    extern __shared__ char smem[];

    const int t    = threadIdx.x;
    const int lane = t & 31;
    const int wid  = t >> 5;
    const int m0   = blockIdx.y * 128;
    const int n0   = blockIdx.x * 128;
    const int z    = blockIdx.z;

    const bf16* Ahp = Ah + (size_t)z * aSz;
    const bf16* Alp = SPLIT ? (Al + (size_t)z * aSz) : nullptr;
    const bf16* Bhp = Bh + (size_t)z * bSz;
    const bf16* Blp = SPLIT ? (Bl + (size_t)z * bSz) : nullptr;
    float*      Cp  = C ? (C + (size_t)z * cSz) : nullptr;

    const int m0w = (wid & 1) * 64;
    const int n0w = (wid >> 1) * 32;

    const uint32_t smemU = (uint32_t)__cvta_generic_to_shared(smem);

    float acc[4][4][4] = {};
    const int nch = K >> 5;

    const int ar0 = t >> 2, ac0 = t & 3;
    const int br0 = t >> 4, bc0 = t & 15;

    auto load_stage = [&](int buf, int kc) {
        const int kg = kc << 5;
        const uint32_t sb = smemU + buf * STAGE_B;
#pragma unroll
        for (int i = 0; i < 2; i++) {
            int r = ar0 + i * 64, c = ac0;
            uint32_t dst = sb + r * 80 + c * 16;
            cp16_s(dst, Ahp + (size_t)(m0 + r) * lda + kg + c * 8);
            if (SPLIT)
                cp16_s(dst + A_TILE_B, Alp + (size_t)(m0 + r) * lda + kg + c * 8);
        }
#pragma unroll
        for (int i = 0; i < 2; i++) {
            int r = br0 + i * 16, c = bc0;
            uint32_t dst = sb + 2 * A_TILE_B + r * 256 + ((c ^ (r & 7)) * 16);
            cp16_s(dst, Bhp + (size_t)(kg + r) * ldb + n0 + c * 8);
            if (SPLIT)
                cp16_s(dst + B_TILE_B, Blp + (size_t)(kg + r) * ldb + n0 + c * 8);
        }
    };

    auto compute_stage = [&](int buf) {
        const uint32_t sb = smemU + buf * STAGE_B;
        const uint32_t aBase = sb + (m0w + (lane & 15)) * 80 + (lane >> 4) * 16;
        const int krow0 = lane & 15;
        const int chAdd = (n0w >> 3) + (lane >> 4);
#pragma unroll
        for (int ks = 0; ks < 2; ks++) {
            uint32_t a[4][4];
            uint32_t b0[4][2], b1[4][2];
            const int krow = ks * 16 + krow0;
#pragma unroll
            for (int mt = 0; mt < 4; mt++) {
                uint32_t addr = aBase + mt * (16 * 80) + ks * 32;
                ldsm4(a[mt][0], a[mt][1], a[mt][2], a[mt][3], addr);
            }
#pragma unroll
            for (int nt = 0; nt < 2; nt++) {
                int ch = (chAdd + nt * 2) ^ (krow & 7);
                uint32_t addr = sb + 2 * A_TILE_B + krow * 256 + ch * 16;
                uint32_t r0, r1, r2, r3;
                ldsm4t(r0, r1, r2, r3, addr);
                b0[nt * 2][0] = r0;  b0[nt * 2][1] = r1;
                b0[nt * 2 + 1][0] = r2;  b0[nt * 2 + 1][1] = r3;
            }
#pragma unroll
            for (int mt = 0; mt < 4; mt++)
#pragma unroll
                for (int nj = 0; nj < 4; nj++)
                    mma16816(acc[mt][nj], a[mt], b0[nj]);

            if (SPLIT) {
#pragma unroll
                for (int nt = 0; nt < 2; nt++) {
                    int ch = (chAdd + nt * 2) ^ (krow & 7);
                    uint32_t addr = sb + 2 * A_TILE_B + B_TILE_B + krow * 256 + ch * 16;
                    uint32_t r0, r1, r2, r3;
                    ldsm4t(r0, r1, r2, r3, addr);
                    b1[nt * 2][0] = r0;  b1[nt * 2][1] = r1;
                    b1[nt * 2 + 1][0] = r2;  b1[nt * 2 + 1][1] = r3;
                }
#pragma unroll
                for (int mt = 0; mt < 4; mt++)
#pragma unroll
                    for (int nj = 0; nj < 4; nj++)
                        mma16816(acc[mt][nj], a[mt], b1[nj]);
#pragma unroll
                for (int mt = 0; mt < 4; mt++) {
                    uint32_t addr = aBase + A_TILE_B + mt * (16 * 80) + ks * 32;
                    ldsm4(a[mt][0], a[mt][1], a[mt][2], a[mt][3], addr);
                }
#pragma unroll
                for (int mt = 0; mt < 4; mt++)
#pragma unroll
                    for (int nj = 0; nj < 4; nj++)
                        mma16816(acc[mt][nj], a[mt], b0[nj]);
            }
        }
    };

    load_stage(0, 0); cp_commit();
    load_stage(1, 1); cp_commit();
    cp_wait<1>();
    __syncthreads();

    for (int i = 0; i < nch; i++) {
        if (i + 2 < nch) load_stage((i + 2) % STAGES, i + 2);
        cp_commit();
        compute_stage(i % STAGES);
        cp_wait<1>();
        __syncthreads();
    }

    // epilogue
#pragma unroll
    for (int mt = 0; mt < 4; mt++) {
        int r0 = m0 + m0w + mt * 16 + (lane >> 2);
        int r1 = r0 + 8;
#pragma unroll
        for (int nj = 0; nj < 4; nj++) {
            int c = n0 + n0w + nj * 8 + (lane & 3) * 2;
            float2 v0 = make_float2(acc[mt][nj][0], acc[mt][nj][1]);
            float2 v1 = make_float2(acc[mt][nj][2], acc[mt][nj][3]);
            if (EPI == 3 || EPI == 6) {
                float2 bz = *(const float2*)&bias[c];
                v0.x += bz.x; v0.y += bz.y;
                v1.x += bz.x; v1.y += bz.y;
            }
            if (EPI == 3) {
                float2 d0 = *(const float2*)&D[(size_t)r0 * N + c];
                float2 d1 = *(const float2*)&D[(size_t)r1 * N + c];
                v0.x = fmaxf(v0.x + d0.x, 0.f); v0.y = fmaxf(v0.y + d0.y, 0.f);
                v1.x = fmaxf(v1.x + d1.x, 0.f); v1.y = fmaxf(v1.y + d1.y, 0.f);
            }
            if (EPI == 7) {
                float2 d0 = *(const float2*)&D[(size_t)r0 * N + c];
                float2 d1 = *(const float2*)&D[(size_t)r1 * N + c];
                float2 bz = *(const float2*)&bias[c];
                v0.x = fmaf(v0.x, alpha, d0.x + bz.x); v0.y = fmaf(v0.y, alpha, d0.y + bz.y);
                v1.x = fmaf(v1.x, alpha, d1.x + bz.x); v1.y = fmaf(v1.y, alpha, d1.y + bz.y);
            }
            if (EPI == 5 || EPI == 6) {
                split2_store(OHi, OLo, (size_t)r0 * ldo + c, v0);
                split2_store(OHi, OLo, (size_t)r1 * ldo + c, v1);
            } else {
                *(float2*)&Cp[(size_t)r0 * N + c] = v0;
                *(float2*)&Cp[(size_t)r1 * N + c] = v1;
            }
        }
    }
}

// ---------------------------------------------------------------------------
// Elementwise / conversion kernels
// ---------------------------------------------------------------------------
__device__ __forceinline__ void split4_store(bf16* hi, bf16* lo, size_t i4, float4 v) {
    bf16 hx = __float2bfloat16(v.x), hy = __float2bfloat16(v.y);
    bf16 hz = __float2bfloat16(v.z), hw = __float2bfloat16(v.w);
    bf16 lx = __float2bfloat16(v.x - __bfloat162float(hx));
    bf16 ly = __float2bfloat16(v.y - __bfloat162float(hy));
    bf16 lz = __float2bfloat16(v.z - __bfloat162float(hz));
    bf16 lw = __float2bfloat16(v.w - __bfloat162float(hw));
    ((__nv_bfloat162*)hi)[2 * i4]     = __halves2bfloat162(hx, hy);
    ((__nv_bfloat162*)hi)[2 * i4 + 1] = __halves2bfloat162(hz, hw);
    ((__nv_bfloat162*)lo)[2 * i4]     = __halves2bfloat162(lx, ly);
    ((__nv_bfloat162*)lo)[2 * i4 + 1] = __halves2bfloat162(lz, lw);
}

__global__ void split_kernel(const float* __restrict__ src, bf16* __restrict__ hi,
                             bf16* __restrict__ lo)
{
    size_t g = (size_t)blockIdx.x * blockDim.x + threadIdx.x;
    float4 v0 = ((const float4*)src)[2 * g];
    float4 v1 = ((const float4*)src)[2 * g + 1];
    split4_store(hi, lo, 2 * g, v0);
    split4_store(hi, lo, 2 * g + 1, v1);
}

// split + transpose fp32 src [R,C] -> hiT/loT [C,R]
__global__ void splitT_kernel(const float* __restrict__ src, bf16* __restrict__ hiT,
                              bf16* __restrict__ loT, int R, int Cc)
{
    __shared__ float tile[32][33];
    int c0 = blockIdx.x * 32, r0 = blockIdx.y * 32;
    int tx = threadIdx.x, ty = threadIdx.y;
    for (int i = ty; i < 32; i += 8)
        tile[i][tx] = src[(size_t)(r0 + i) * Cc + c0 + tx];
    __syncthreads();
    for (int i = ty; i < 32; i += 8) {
        float v = tile[tx][i];
        bf16 h = __float2bfloat16(v);
        bf16 l = __float2bfloat16(v - __bfloat162float(h));
        size_t o = (size_t)(c0 + i) * R + r0 + tx;
        hiT[o] = h; loT[o] = l;
    }
}

// transpose a bf16 hi/lo pair: [R,C] -> [C,R]
__global__ void transbf2_kernel(const bf16* __restrict__ hi, const bf16* __restrict__ lo,
                                bf16* __restrict__ hiT, bf16* __restrict__ loT,
                                int R, int Cc)
{
    __shared__ bf16 th[32][33], tl[32][33];
    int c0 = blockIdx.x * 32, r0 = blockIdx.y * 32;
    int tx = threadIdx.x, ty = threadIdx.y;
    for (int i = ty; i < 32; i += 8) {
        size_t s = (size_t)(r0 + i) * Cc + c0 + tx;
        th[i][tx] = hi[s];
        tl[i][tx] = lo[s];
    }
    __syncthreads();
    for (int i = ty; i < 32; i += 8) {
        size_t o = (size_t)(c0 + i) * R + r0 + tx;
        hiT[o] = th[tx][i];
        loT[o] = tl[tx][i];
    }
}

__global__ void zero_kernel(float* __restrict__ p, int n)
{
    int i = blockIdx.x * blockDim.x + threadIdx.x;
    if (i < n) p[i] = 0.f;
}

__global__ void rowsum_kernel(const float* __restrict__ A, float* __restrict__ rowv)
{
    int warp = threadIdx.x >> 5, lane = threadIdx.x & 31;
    int row = blockIdx.x * 8 + warp;
    const float4* p = (const float4*)(A + (size_t)row * NN);
    float s = 0.f;
#pragma unroll
    for (int i = 0; i < 32; i++) {
        float4 v = p[lane + i * 32];
        s += v.x + v.y + v.z + v.w;
    }
#pragma unroll
    for (int o = 16; o; o >>= 1) s += __shfl_down_sync(0xffffffffu, s, o);
    if (!lane) rowv[row] = s;
}

__global__ void colsum_kernel(const float* __restrict__ A, float* __restrict__ colv)
{
    int j = blockIdx.x * 256 + threadIdx.x;
    int i0 = blockIdx.y * 256;
    float s = 0.f;
    for (int i = 0; i < 256; i++) s += A[(size_t)(i0 + i) * NN + j];
    atomicAdd(&colv[j], s);
}

__global__ void build_nnz_kernel(const float* __restrict__ A, int* __restrict__ idx,
                                 int* __restrict__ cnt)
{
    int row = blockIdx.x;
    __shared__ int c;
    if (threadIdx.x == 0) c = 0;
    __syncthreads();
    for (int col = threadIdx.x; col < NN; col += 256) {
        if (A[(size_t)row * NN + col] != 0.f) {
            int p = atomicAdd(&c, 1);
            if (p < MAXNNZ) idx[(size_t)row * MAXNNZ + p] = col;
        }
    }
    __syncthreads();
    if (threadIdx.x == 0) cnt[row] = (c < MAXNNZ) ? c : MAXNNZ;
}

__global__ void __launch_bounds__(256)
simfuse_sparse_kernel(const float* __restrict__ A, const float* __restrict__ G,
                      const int* __restrict__ idx, const int* __restrict__ cnt,
                      const float* __restrict__ rowv, const float* __restrict__ colv,
                      bf16* __restrict__ Shi, bf16* __restrict__ Slo)
{
    const int row = blockIdx.x;
    const int t = threadIdx.x;

    __shared__ int sidx[MAXNNZ];
    const int n = cnt[row];
    for (int e = t; e < n; e += 256) sidx[e] = idx[(size_t)row * MAXNNZ + e];
    __syncthreads();

    float4 acc[4] = {};
    for (int e = 0; e < n; e++) {
        const float4* Aj = (const float4*)(A + (size_t)sidx[e] * NN);
#pragma unroll
        for (int m = 0; m < 4; m++) {
            float4 v = Aj[t + m * 256];
            acc[m].x += v.x; acc[m].y += v.y; acc[m].z += v.z; acc[m].w += v.w;
        }
    }

    const float r = rowv[row];
    const float4* Ai = (const float4*)(A + (size_t)row * NN);
    const float4* Gi = (const float4*)(G + (size_t)row * NN);
    bf16* hi = Shi + (size_t)row * NN;
    bf16* lo = Slo + (size_t)row * NN;
#pragma unroll
    for (int m = 0; m < 4; m++) {
        int f4 = t + m * 256;
        float4 v = acc[m];
        float4 a = Ai[f4];
        float4 g = Gi[f4];
        float4 c = *(const float4*)&colv[f4 * 4];
        float4 o;
        o.x = v.x / (r + c.x - v.x + 1e-6f) + a.x + g.x;
        o.y = v.y / (r + c.y - v.y + 1e-6f) + a.y + g.y;
        o.z = v.z / (r + c.z - v.z + 1e-6f) + a.z + g.z;
        o.w = v.w / (r + c.w - v.w + 1e-6f) + a.w + g.w;
        split4_store(hi, lo, (size_t)f4, o);
    }
}

__global__ void combine_ln_kernel(const float* __restrict__ P, const float* __restrict__ w,
                                  const float* __restrict__ bstk,
                                  const float* __restrict__ gamma, const float* __restrict__ beta,
                                  bf16* __restrict__ hhi, bf16* __restrict__ hlo)
{
    int n = blockIdx.x, t = threadIdx.x;
    float wn[KW];
#pragma unroll
    for (int k = 0; k < KW; k++) wn[k] = w[n * KW + k];
    float4 v = make_float4(0.f, 0.f, 0.f, 0.f);
#pragma unroll
    for (int k = 0; k < KW; k++) {
        float4 p = ((const float4*)(P + ((size_t)k * NN + n) * DM))[t];
        float4 b = ((const float4*)(bstk + (size_t)k * DM))[t];
        v.x = fmaf(wn[k], p.x + b.x, v.x);
        v.y = fmaf(wn[k], p.y + b.y, v.y);
        v.z = fmaf(wn[k], p.z + b.z, v.z);
        v.w = fmaf(wn[k], p.w + b.w, v.w);
    }
    float s  = v.x + v.y + v.z + v.w;
    float s2 = v.x * v.x + v.y * v.y + v.z * v.z + v.w * v.w;
    __shared__ float sS[8], sS2[8], sMean, sInv;
    int warp = t >> 5, lane = t & 31;
#pragma unroll
    for (int o = 16; o; o >>= 1) {
        s  += __shfl_down_sync(0xffffffffu, s, o);
        s2 += __shfl_down_sync(0xffffffffu, s2, o);
    }
    if (!lane) { sS[warp] = s; sS2[warp] = s2; }
    __syncthreads();
    if (t == 0) {
        float S = 0.f, S2 = 0.f;
        for (int i = 0; i < 8; i++) { S += sS[i]; S2 += sS2[i]; }
        float mean = S * (1.f / DM);
        float var  = S2 * (1.f / DM) - mean * mean;
        sMean = mean;
        sInv  = rsqrtf(var + 1e-5f);
    }
    __syncthreads();
    float mean = sMean, inv = sInv;
    float4 gg = ((const float4*)gamma)[t];
    float4 bb = ((const float4*)beta)[t];
    float4 o;
    o.x = (v.x - mean) * inv * gg.x + bb.x;
    o.y = (v.y - mean) * inv * gg.y + bb.y;
    o.z = (v.z - mean) * inv * gg.z + bb.z;
    o.w = (v.w - mean) * inv * gg.w + bb.w;
    split4_store(hhi + (size_t)n * DM, hlo + (size_t)n * DM, t, o);
}

// wkbq[i] = sum_o Wk[i,o] * bq[o]   (warp per row)
__global__ void wkbq_kernel(const float* __restrict__ Wk, const float* __restrict__ bq,
                            float* __restrict__ wkbq)
{
    int warp = threadIdx.x >> 5, lane = threadIdx.x & 31;
    int row = blockIdx.x * 8 + warp;
    float s = 0.f;
    for (int j = lane; j < DM; j += 32)
        s = fmaf(Wk[(size_t)row * DM + j], bq[j], s);
#pragma unroll
    for (int o = 16; o; o >>= 1) s += __shfl_down_sync(0xffffffffu, s, o);
    if (!lane) wkbq[row] = s;
}

// cbs[m] = (h[m,:] . wkbq) / 32   (warp per row; h = hhi + hlo)
__global__ void colvec_kernel(const bf16* __restrict__ hhi, const bf16* __restrict__ hlo,
                              const float* __restrict__ wkbq, float* __restrict__ cbs)
{
    int warp = threadIdx.x >> 5, lane = threadIdx.x & 31;
    int row = blockIdx.x * 8 + warp;
    float s = 0.f;
    for (int j = lane; j < DM; j += 32) {
        float hv = __bfloat162float(hhi[(size_t)row * DM + j]) +
                   __bfloat162float(hlo[(size_t)row * DM + j]);
        s = fmaf(hv, wkbq[j], s);
    }
#pragma unroll
    for (int o = 16; o; o >>= 1) s += __shfl_down_sync(0xffffffffu, s, o);
    if (!lane) cbs[row] = s * 0.03125f;
}

__global__ void softmax_kernel(const float* __restrict__ S, bf16* __restrict__ Ohi,
                               bf16* __restrict__ Olo)
{
    int r = blockIdx.x, t = threadIdx.x;
    const float4* row = (const float4*)(S + (size_t)r * NN);
    float4 v[4];
    float mx = -1e30f;
#pragma unroll
    for (int i = 0; i < 4; i++) {
        v[i] = row[t + i * 256];
        mx = fmaxf(mx, fmaxf(fmaxf(v[i].x, v[i].y), fmaxf(v[i].z, v[i].w)));
    }
    __shared__ float sh[8];
    __shared__ float sbc;
    int warp = t >> 5, lane = t & 31;
#pragma unroll
    for (int o = 16; o; o >>= 1) mx = fmaxf(mx, __shfl_xor_sync(0xffffffffu, mx, o));
    if (!lane) sh[warp] = mx;
    __syncthreads();
    if (t == 0) {
        float m = sh[0];
        for (int i = 1; i < 8; i++) m = fmaxf(m, sh[i]);
        sbc = m;
    }
    __syncthreads();
    mx = sbc;
    float s = 0.f;
#pragma unroll
    for (int i = 0; i < 4; i++) {
        v[i].x = __expf(v[i].x - mx);
        v[i].y = __expf(v[i].y - mx);
        v[i].z = __expf(v[i].z - mx);
        v[i].w = __expf(v[i].w - mx);
        s += v[i].x + v[i].y + v[i].z + v[i].w;
    }
#pragma unroll
    for (int o = 16; o; o >>= 1) s += __shfl_xor_sync(0xffffffffu, s, o);
    __syncthreads();
    if (!lane) sh[warp] = s;
    __syncthreads();
    if (t == 0) {
        float z = 0.f;
        for (int i = 0; i < 8; i++) z += sh[i];
        sbc = 1.f / z;
    }
    __syncthreads();
    float inv = sbc;
    bf16* hi = Ohi + (size_t)r * NN;
    bf16* lo = Olo + (size_t)r * NN;
#pragma unroll
    for (int i = 0; i < 4; i++) {
        float4 o;
        o.x = v[i].x * inv; o.y = v[i].y * inv; o.z = v[i].z * inv; o.w = v[i].w * inv;
        split4_store(hi, lo, (size_t)(t + i * 256), o);
    }
}

// ---------------------------------------------------------------------------
// Host launcher
// ---------------------------------------------------------------------------
extern "C" void kernel_launch(void* const* d_in, const int* in_sizes, int n_in,
                              void* d_out, int out_size)
{
    const float* x     = (const float*)d_in[0];
    const float* A     = (const float*)d_in[1];
    const float* G     = (const float*)d_in[2];
    const float* w     = (const float*)d_in[3];
    const float* Wstk  = (const float*)d_in[4];
    const float* bstk  = (const float*)d_in[5];
    const float* Wq    = (const float*)d_in[6];
    const float* bq    = (const float*)d_in[7];
    const float* Wk    = (const float*)d_in[8];
    const float* bk    = (const float*)d_in[9];   // cancels under row softmax
    const float* Wv    = (const float*)d_in[10];
    const float* bv    = (const float*)d_in[11];
    const float* Wo    = (const float*)d_in[12];
    const float* bo    = (const float*)d_in[13];
    const float* gamma = (const float*)d_in[14];
    const float* beta  = (const float*)d_in[15];
    float* out = (float*)d_out;
    (void)bk;

    float *dng, *scores, *P, *wkbq, *cbs, *rowv, *colv;
    int *nnzidx, *nnzcnt;
    bf16 *Shi, *Slo, *xhi, *xlo, *athi, *atlo, *Wshi, *Wslo, *hhi, *hlo;
    bf16 *hThi, *hTlo, *G1hi, *G1lo, *Vhi, *Vlo, *aohi, *aolo;
    bf16 *Wqhi, *Wqlo, *WkThi, *WkTlo, *Wvhi, *Wvlo, *Mhi, *Mlo, *Wohi, *Wolo;
    cudaGetSymbolAddress((void**)&dng, g_dng);
    cudaGetSymbolAddress((void**)&scores, g_scores);
    cudaGetSymbolAddress((void**)&P, g_P);
    cudaGetSymbolAddress((void**)&wkbq, g_wkbq);
    cudaGetSymbolAddress((void**)&cbs, g_cbs);
    cudaGetSymbolAddress((void**)&rowv, g_row);
    cudaGetSymbolAddress((void**)&colv, g_col);
    cudaGetSymbolAddress((void**)&nnzidx, g_nnzidx);
    cudaGetSymbolAddress((void**)&nnzcnt, g_nnzcnt);
    cudaGetSymbolAddress((void**)&Shi, g_Shi);
    cudaGetSymbolAddress((void**)&Slo, g_Slo);
    cudaGetSymbolAddress((void**)&xhi, g_xhi);
    cudaGetSymbolAddress((void**)&xlo, g_xlo);
    cudaGetSymbolAddress((void**)&athi, g_athi);
    cudaGetSymbolAddress((void**)&atlo, g_atlo);
    cudaGetSymbolAddress((void**)&Wshi, g_Wshi);
    cudaGetSymbolAddress((void**)&Wslo, g_Wslo);
    cudaGetSymbolAddress((void**)&hhi, g_hhi);
    cudaGetSymbolAddress((void**)&hlo, g_hlo);
    cudaGetSymbolAddress((void**)&hThi, g_hThi);
    cudaGetSymbolAddress((void**)&hTlo, g_hTlo);
    cudaGetSymbolAddress((void**)&G1hi, g_G1hi);
    cudaGetSymbolAddress((void**)&G1lo, g_G1lo);
    cudaGetSymbolAddress((void**)&Vhi, g_Vhi);
    cudaGetSymbolAddress((void**)&Vlo, g_Vlo);
    cudaGetSymbolAddress((void**)&aohi, g_aohi);
    cudaGetSymbolAddress((void**)&aolo, g_aolo);
    cudaGetSymbolAddress((void**)&Wqhi, g_Wqhi);
    cudaGetSymbolAddress((void**)&Wqlo, g_Wqlo);
    cudaGetSymbolAddress((void**)&WkThi, g_WkThi);
    cudaGetSymbolAddress((void**)&WkTlo, g_WkTlo);
    cudaGetSymbolAddress((void**)&Wvhi, g_Wvhi);
    cudaGetSymbolAddress((void**)&Wvlo, g_Wvlo);
    cudaGetSymbolAddress((void**)&Mhi, g_Mhi);
    cudaGetSymbolAddress((void**)&Mlo, g_Mlo);
    cudaGetSymbolAddress((void**)&Wohi, g_Wohi);
    cudaGetSymbolAddress((void**)&Wolo, g_Wolo);

    cudaFuncSetAttribute(bgemm<0, true>, cudaFuncAttributeMaxDynamicSharedMemorySize, GEMM_SMEM);
    cudaFuncSetAttribute(bgemm<3, true>, cudaFuncAttributeMaxDynamicSharedMemorySize, GEMM_SMEM);
    cudaFuncSetAttribute(bgemm<5, true>, cudaFuncAttributeMaxDynamicSharedMemorySize, GEMM_SMEM);
    cudaFuncSetAttribute(bgemm<6, true>, cudaFuncAttributeMaxDynamicSharedMemorySize, GEMM_SMEM);
    cudaFuncSetAttribute(bgemm<7, true>, cudaFuncAttributeMaxDynamicSharedMemorySize, GEMM_SMEM);

    const size_t NDM = (size_t)NN * DM;
    const bool fork = (g_s2 != nullptr) && (g_evF != nullptr) && (g_evJ != nullptr) &&
                      (g_evM != nullptr);
    cudaStream_t sB = fork ? g_s2 : (cudaStream_t)0;
    dim3 tb(32, 8);

    // ======================= sB head: Wstk split (gates P) ===================
    split_kernel<<<(int)(KW * NDM / 4 / 512), 256, 0, sB>>>(Wstk, Wshi, Wslo);

    // ======================= stream 0: x + attention weights ================
    split_kernel<<<NN * (NN / 4) / 512, 256>>>(x, xhi, xlo);
    if (fork) cudaEventRecord(g_evF, 0);

    wkbq_kernel<<<DM / 8, 256>>>(Wk, bq, wkbq);
    split_kernel<<<DM * (DM / 4) / 512, 256>>>(Wq, Wqhi, Wqlo);
    splitT_kernel<<<dim3(DM / 32, DM / 32), tb>>>(Wk, WkThi, WkTlo, DM, DM);
    split_kernel<<<DM * (DM / 4) / 512, 256>>>(Wv, Wvhi, Wvlo);
    // M = Wq @ Wk^T  (split-stored)
    bgemm<5, true><<<dim3(8, 8), 256, GEMM_SMEM>>>(
        Wqhi, Wqlo, WkThi, WkTlo, nullptr, nullptr, nullptr, Mhi, Mlo,
        DM, DM, DM, DM, DM, DM, 0, 0, 0, 1.f);
    if (fork) cudaEventRecord(g_evM, 0);

    split_kernel<<<DM * (NN / 4) / 512, 256>>>(Wo, Wohi, Wolo);

    // ======================= chain B spine (stream sB) ======================
    if (fork) cudaStreamWaitEvent(sB, g_evF, 0);

    // P_k = x @ W_k (batched)
    bgemm<0, true><<<dim3(8, 32, KW), 256, GEMM_SMEM, sB>>>(
        xhi, xlo, Wshi, Wslo, P, nullptr, nullptr, nullptr, nullptr,
        NN, DM, NN, NN, DM, 0, 0, NDM, NDM, 1.f);

    combine_ln_kernel<<<NN, 256, 0, sB>>>(P, w, bstk, gamma, beta, hhi, hlo);

    if (fork) cudaStreamWaitEvent(sB, g_evM, 0);
    colvec_kernel<<<NN / 8, 256, 0, sB>>>(hhi, hlo, wkbq, cbs);

    // G1 = h @ M  (split-stored)
    bgemm<5, true><<<dim3(8, 32), 256, GEMM_SMEM, sB>>>(
        hhi, hlo, Mhi, Mlo, nullptr, nullptr, nullptr, G1hi, G1lo,
        NN, DM, DM, DM, DM, DM, 0, 0, 0, 1.f);

    // V = h @ Wv + bv  (split-stored)
    bgemm<6, true><<<dim3(8, 32), 256, GEMM_SMEM, sB>>>(
        hhi, hlo, Wvhi, Wvlo, nullptr, nullptr, bv, Vhi, Vlo,
        NN, DM, DM, DM, DM, DM, 0, 0, 0, 1.f);

    // h^T (bf16 pair transpose)
    transbf2_kernel<<<dim3(DM / 32, NN / 32), tb, 0, sB>>>(hhi, hlo, hThi, hTlo, NN, DM);

    if (fork) cudaEventRecord(g_evJ, sB);

    // ======================= chain A (stream 0) =============================
    zero_kernel<<<16, 256>>>(colv, NN);
    build_nnz_kernel<<<NN, 256>>>(A, nnzidx, nnzcnt);
    rowsum_kernel<<<NN / 8, 256>>>(A, rowv);
    colsum_kernel<<<dim3(16, 16), 256>>>(A, colv);
    simfuse_sparse_kernel<<<NN, 256>>>(A, G, nnzidx, nnzcnt, rowv, colv, Shi, Slo);

    // dng = S @ x
    bgemm<0, true><<<dim3(32, 32), 256, GEMM_SMEM>>>(
        Shi, Slo, xhi, xlo, dng, nullptr, nullptr, nullptr, nullptr,
        NN, NN, NN, NN, NN, 0, 0, 0, 0, 1.f);

    // ======================= join ==========================================
    if (fork) cudaStreamWaitEvent(0, g_evJ, 0);

    // scores = G1 @ h^T / 32 + dng + cbs[col]
    bgemm<7, true><<<dim3(32, 32), 256, GEMM_SMEM>>>(
        G1hi, G1lo, hThi, hTlo, scores, dng, cbs, nullptr, nullptr,
        NN, NN, DM, DM, NN, 0, 0, 0, 0, 0.03125f);

    softmax_kernel<<<NN, 256>>>(scores, athi, atlo);

    // ao = attn @ V   (V row-major [NN, DM] is exactly B [K,N])
    bgemm<5, true><<<dim3(8, 32), 256, GEMM_SMEM>>>(
        athi, atlo, Vhi, Vlo, nullptr, nullptr, nullptr, aohi, aolo,
        NN, DM, NN, NN, DM, DM, 0, 0, 0, 1.f);

    // out = relu(ao @ Wo + bo + dng)
    bgemm<3, true><<<dim3(32, 32), 256, GEMM_SMEM>>>(
        aohi, aolo, Wohi, Wolo, out, dng, bo, nullptr, nullptr,
        NN, NN, DM, DM, NN, 0, 0, 0, 0, 1.f);
}